// round 1
// baseline (speedup 1.0000x reference)
#include <cuda_runtime.h>
#include <math.h>

#define BATCH 2
#define SEQ 2048
#define DMODEL 2048
#define NH 8
#define HDIM 256
#define MROWS (BATCH * SEQ)          // 4096
#define QKSTR 257                    // padded smem row stride (conflict-free scalar LDS)

// Scratch (static device arrays: allocation-free per harness rules)
static __device__ float g_q[MROWS * NH * HDIM];   // 33.5 MB  [B*S, H*HD]
static __device__ float g_k[MROWS * HDIM];        // 4.2 MB   [B*S, HD]
static __device__ float g_v[MROWS * HDIM];        // 4.2 MB
static __device__ float g_ao[MROWS * NH * HDIM];  // 33.5 MB  attention output, [B*S, H*HD]

// ---------------------------------------------------------------------------
// SGEMM: C[M,N] = A[M,K] @ B[K,N], all row-major fp32.
// Tiles: 128x128x8, 256 threads, 8x8 per-thread micro-tile (split 4+4 cols to
// keep Bs smem reads at worst 2-way conflicted).
// Requires M%128==0, N%128==0, K%8==0 (true for all launches here).
// ---------------------------------------------------------------------------
__global__ void __launch_bounds__(256, 2)
sgemm128(const float* __restrict__ A, const float* __restrict__ Bm,
         float* __restrict__ C, int M, int N, int K) {
    __shared__ float As[8][128];
    __shared__ float Bs[8][132];
    const int tid = threadIdx.x;
    const int tx = tid & 15, ty = tid >> 4;
    const int brow = blockIdx.y * 128;
    const int bcol = blockIdx.x * 128;

    float acc[8][8];
#pragma unroll
    for (int i = 0; i < 8; i++)
#pragma unroll
        for (int j = 0; j < 8; j++) acc[i][j] = 0.f;

    const int ar = tid >> 1;           // A row within tile (0..127)
    const int ac = (tid & 1) * 4;      // A k-offset (0 or 4)
    const int br = tid >> 5;           // B k-row (0..7)
    const int bc = (tid & 31) * 4;     // B col offset (0..124)

    for (int k0 = 0; k0 < K; k0 += 8) {
        float4 av = *(const float4*)(A + (size_t)(brow + ar) * K + k0 + ac);
        As[ac + 0][ar] = av.x;
        As[ac + 1][ar] = av.y;
        As[ac + 2][ar] = av.z;
        As[ac + 3][ar] = av.w;
        float4 bv = *(const float4*)(Bm + (size_t)(k0 + br) * N + bcol + bc);
        *(float4*)&Bs[br][bc] = bv;
        __syncthreads();
#pragma unroll
        for (int kk = 0; kk < 8; kk++) {
            float a[8], b[8];
            *(float4*)&a[0] = *(const float4*)&As[kk][ty * 8];
            *(float4*)&a[4] = *(const float4*)&As[kk][ty * 8 + 4];
            *(float4*)&b[0] = *(const float4*)&Bs[kk][tx * 4];
            *(float4*)&b[4] = *(const float4*)&Bs[kk][64 + tx * 4];
#pragma unroll
            for (int i = 0; i < 8; i++)
#pragma unroll
                for (int j = 0; j < 8; j++) acc[i][j] += a[i] * b[j];
        }
        __syncthreads();
    }
#pragma unroll
    for (int i = 0; i < 8; i++) {
        float* crow = C + (size_t)(brow + ty * 8 + i) * N + bcol;
        float4 v0 = make_float4(acc[i][0], acc[i][1], acc[i][2], acc[i][3]);
        float4 v1 = make_float4(acc[i][4], acc[i][5], acc[i][6], acc[i][7]);
        *(float4*)(crow + tx * 4) = v0;
        *(float4*)(crow + 64 + tx * 4) = v1;
    }
}

// ---------------------------------------------------------------------------
// RoPE applied in-place to g_q (8 heads) and g_k (1 head). Double-precision
// angle: |angle| reaches ~2047 rad, so fp32 argument reduction would cost
// accuracy we don't need to give up.
// ---------------------------------------------------------------------------
__global__ void rope_kernel(const int* __restrict__ pos_ids) {
    int idx = blockIdx.x * blockDim.x + threadIdx.x;
    const int total = MROWS * 9 * 128;  // 8 q-heads + 1 k-head, 128 pairs each
    if (idx >= total) return;
    int i = idx & 127;
    int rest = idx >> 7;
    int h = rest % 9;
    int bs = rest / 9;

    double pos = (double)pos_ids[bs];
    double freq = pow(10000.0, -(double)i / 128.0);   // 10000^(-2i/HD)
    double ang = pos * freq;
    double cd, sd;
    sincos(ang, &sd, &cd);
    float c = (float)cd, s = (float)sd;

    float* base = (h < 8) ? (g_q + (size_t)bs * (NH * HDIM) + h * HDIM)
                          : (g_k + (size_t)bs * HDIM);
    float x0 = base[i];
    float x1 = base[i + 128];
    base[i]       = x0 * c - x1 * s;
    base[i + 128] = x1 * c + x0 * s;
}

// ---------------------------------------------------------------------------
// Flash attention (fp32, online softmax). One block = 64 queries for one
// (b, h). K/V shared across heads (MQA). Tiles of 64 keys staged in smem.
// Thread layout 16x16: scores phase each thread owns a 4x4 score micro-tile;
// PV phase each thread owns 4 rows x 16 hd-columns (col = tx + 16*j, which is
// bank-conflict-free for the padded V reads).
// ---------------------------------------------------------------------------
#define FLASH_SMEM_FLOATS (2 * 64 * QKSTR + 64 * 65 + 3 * 64)
#define FLASH_SMEM_BYTES  (FLASH_SMEM_FLOATS * 4)

__global__ void __launch_bounds__(256)
flash_attn(const float* __restrict__ mask) {
    extern __shared__ float sm[];
    float* qs     = sm;                       // [64][257]
    float* kvs    = sm + 64 * QKSTR;          // [64][257] (K then reused for V)
    float* ps     = sm + 2 * 64 * QKSTR;      // [64][65]  exp'd probabilities
    float* m_s    = ps + 64 * 65;             // [64] running max
    float* l_s    = m_s + 64;                 // [64] running denom
    float* corr_s = l_s + 64;                 // [64] per-tile rescale

    const int tid = threadIdx.x;
    const int tx = tid & 15, ty = tid >> 4;
    const int q0 = blockIdx.x * 64;
    const int bh = blockIdx.y;
    const int b = bh >> 3, h = bh & 7;

    // Load Q tile (64 x 256) into padded smem
    const float* qg = g_q + (size_t)(b * SEQ + q0) * (NH * HDIM) + h * HDIM;
    for (int t = tid; t < 64 * 64; t += 256) {
        int r = t >> 6;
        int c4 = (t & 63) * 4;
        float4 v = *(const float4*)(qg + (size_t)r * (NH * HDIM) + c4);
        float* dst = qs + r * QKSTR + c4;
        dst[0] = v.x; dst[1] = v.y; dst[2] = v.z; dst[3] = v.w;
    }
    if (tid < 64) { m_s[tid] = -1e30f; l_s[tid] = 0.f; }

    float o[4][16];
#pragma unroll
    for (int i = 0; i < 4; i++)
#pragma unroll
        for (int j = 0; j < 16; j++) o[i][j] = 0.f;
    __syncthreads();

    for (int k0 = 0; k0 < SEQ; k0 += 64) {
        // ---- load K tile ----
        const float* kg = g_k + (size_t)(b * SEQ + k0) * HDIM;
        for (int t = tid; t < 64 * 64; t += 256) {
            int r = t >> 6;
            int c4 = (t & 63) * 4;
            float4 v = *(const float4*)(kg + (size_t)r * HDIM + c4);
            float* dst = kvs + r * QKSTR + c4;
            dst[0] = v.x; dst[1] = v.y; dst[2] = v.z; dst[3] = v.w;
        }
        __syncthreads();

        // ---- scores: 4x4 per thread, K-dim = 256 ----
        float s[4][4];
#pragma unroll
        for (int i = 0; i < 4; i++)
#pragma unroll
            for (int j = 0; j < 4; j++) s[i][j] = 0.f;

        const float* qrow = qs + (ty * 4) * QKSTR;
        const float* krow = kvs + (tx * 4) * QKSTR;
#pragma unroll 8
        for (int d = 0; d < 256; d++) {
            float a0 = qrow[d];
            float a1 = qrow[QKSTR + d];
            float a2 = qrow[2 * QKSTR + d];
            float a3 = qrow[3 * QKSTR + d];
            float b0 = krow[d];
            float b1 = krow[QKSTR + d];
            float b2 = krow[2 * QKSTR + d];
            float b3 = krow[3 * QKSTR + d];
            s[0][0] += a0 * b0; s[0][1] += a0 * b1; s[0][2] += a0 * b2; s[0][3] += a0 * b3;
            s[1][0] += a1 * b0; s[1][1] += a1 * b1; s[1][2] += a1 * b2; s[1][3] += a1 * b3;
            s[2][0] += a2 * b0; s[2][1] += a2 * b1; s[2][2] += a2 * b2; s[2][3] += a2 * b3;
            s[3][0] += a3 * b0; s[3][1] += a3 * b1; s[3][2] += a3 * b2; s[3][3] += a3 * b3;
        }

        // ---- online softmax (rows ty*4+i, 16 tx threads per row) ----
        const float* mrow = mask + (size_t)b * SEQ * SEQ
                                 + (size_t)(q0 + ty * 4) * SEQ + (k0 + tx * 4);
#pragma unroll
        for (int i = 0; i < 4; i++) {
            int r = ty * 4 + i;
            float sv[4];
#pragma unroll
            for (int j = 0; j < 4; j++)
                sv[j] = s[i][j] * 0.0625f + mrow[(size_t)i * SEQ + j];  // /sqrt(256)
            float mx = fmaxf(fmaxf(sv[0], sv[1]), fmaxf(sv[2], sv[3]));
#pragma unroll
            for (int off = 8; off >= 1; off >>= 1)
                mx = fmaxf(mx, __shfl_xor_sync(0xffffffffu, mx, off, 16));
            float m_old = m_s[r];
            float m_new = fmaxf(m_old, mx);
            float sum = 0.f;
#pragma unroll
            for (int j = 0; j < 4; j++) {
                float p = __expf(sv[j] - m_new);
                ps[r * 65 + tx * 4 + j] = p;
                sum += p;
            }
#pragma unroll
            for (int off = 8; off >= 1; off >>= 1)
                sum += __shfl_xor_sync(0xffffffffu, sum, off, 16);
            if (tx == 0) {
                float corr = __expf(m_old - m_new);
                corr_s[r] = corr;
                l_s[r] = l_s[r] * corr + sum;
                m_s[r] = m_new;
            }
        }
        __syncthreads();

        // ---- rescale o, load V tile (reuse kvs) ----
#pragma unroll
        for (int i = 0; i < 4; i++) {
            float corr = corr_s[ty * 4 + i];
#pragma unroll
            for (int j = 0; j < 16; j++) o[i][j] *= corr;
        }
        const float* vg = g_v + (size_t)(b * SEQ + k0) * HDIM;
        for (int t = tid; t < 64 * 64; t += 256) {
            int r = t >> 6;
            int c4 = (t & 63) * 4;
            float4 v = *(const float4*)(vg + (size_t)r * HDIM + c4);
            float* dst = kvs + r * QKSTR + c4;
            dst[0] = v.x; dst[1] = v.y; dst[2] = v.z; dst[3] = v.w;
        }
        __syncthreads();

        // ---- PV: o[4][16] += P[4][64] @ V[64][16] ----
        const float* psr = ps + (ty * 4) * 65;
        for (int kk = 0; kk < 64; kk++) {
            float p0 = psr[kk];
            float p1 = psr[65 + kk];
            float p2 = psr[130 + kk];
            float p3 = psr[195 + kk];
            const float* vr = kvs + kk * QKSTR + tx;
#pragma unroll
            for (int j = 0; j < 16; j++) {
                float vv = vr[16 * j];
                o[0][j] += p0 * vv;
                o[1][j] += p1 * vv;
                o[2][j] += p2 * vv;
                o[3][j] += p3 * vv;
            }
        }
        __syncthreads();
    }

    // ---- epilogue: normalize and write to [B*S, H*HD] ----
#pragma unroll
    for (int i = 0; i < 4; i++) {
        int r = ty * 4 + i;
        float inv = 1.0f / l_s[r];
        float* og = g_ao + (size_t)(b * SEQ + q0 + r) * (NH * HDIM) + h * HDIM;
#pragma unroll
        for (int j = 0; j < 16; j++)
            og[tx + 16 * j] = o[i][j] * inv;
    }
}

// ---------------------------------------------------------------------------
extern "C" void kernel_launch(void* const* d_in, const int* in_sizes, int n_in,
                              void* d_out, int out_size) {
    const float* hidden = (const float*)d_in[0];
    const float* mask   = (const float*)d_in[1];
    const int*   pos    = (const int*)d_in[2];
    const float* Wq     = (const float*)d_in[3];
    const float* Wk     = (const float*)d_in[4];
    const float* Wv     = (const float*)d_in[5];
    const float* Wo     = (const float*)d_in[6];
    float* out = (float*)d_out;

    float *qb, *kb, *vb, *aob;
    cudaGetSymbolAddress((void**)&qb, g_q);
    cudaGetSymbolAddress((void**)&kb, g_k);
    cudaGetSymbolAddress((void**)&vb, g_v);
    cudaGetSymbolAddress((void**)&aob, g_ao);

    cudaFuncSetAttribute(flash_attn, cudaFuncAttributeMaxDynamicSharedMemorySize,
                         FLASH_SMEM_BYTES);

    // Q/K/V projections
    dim3 gq(DMODEL / 128, MROWS / 128);      // (16, 32)
    sgemm128<<<gq, 256>>>(hidden, Wq, qb, MROWS, NH * HDIM, DMODEL);
    dim3 gkv(HDIM / 128, MROWS / 128);       // (2, 32)
    sgemm128<<<gkv, 256>>>(hidden, Wk, kb, MROWS, HDIM, DMODEL);
    sgemm128<<<gkv, 256>>>(hidden, Wv, vb, MROWS, HDIM, DMODEL);

    // RoPE on q and k
    int rtot = MROWS * 9 * 128;
    rope_kernel<<<(rtot + 255) / 256, 256>>>(pos);

    // Fused attention
    dim3 gf(SEQ / 64, BATCH * NH);           // (32, 16)
    flash_attn<<<gf, 256, FLASH_SMEM_BYTES>>>(mask);

    // Output projection -> d_out
    sgemm128<<<gq, 256>>>(aob, Wo, out, MROWS, DMODEL, DMODEL);
}

// round 2
// speedup vs baseline: 1.2960x; 1.2960x over previous
#include <cuda_runtime.h>
#include <math.h>

#define BATCH 2
#define SEQ 2048
#define DMODEL 2048
#define NH 8
#define HDIM 256
#define MROWS (BATCH * SEQ)          // 4096
#define QKSTR 257                    // padded smem row stride (conflict-free scalar LDS)

// Scratch (static device arrays: allocation-free per harness rules)
static __device__ float g_q[MROWS * NH * HDIM];   // 33.5 MB  [B*S, H*HD]
static __device__ float g_k[MROWS * HDIM];        // 4.2 MB   [B*S, HD]
static __device__ float g_v[MROWS * HDIM];        // 4.2 MB
static __device__ float g_ao[MROWS * NH * HDIM];  // 33.5 MB  attention output
static __device__ float2 g_rope[MROWS * 128];     // 4.2 MB   (cos, sin) per (bs, freq)

// ---------------------------------------------------------------------------
// SGEMM: C[M,N] = A[M,K] @ B[K,N], row-major fp32. 128x128x8 tiles, 256 thr,
// 8x8 micro-tile. Double-buffered smem: one __syncthreads per k-tile, LDG for
// tile t+1 overlaps FFMA on tile t.
// ---------------------------------------------------------------------------
__global__ void __launch_bounds__(256, 2)
sgemm128(const float* __restrict__ A, const float* __restrict__ Bm,
         float* __restrict__ C, int M, int N, int K) {
    __shared__ float As[2][8][128];
    __shared__ float Bs[2][8][132];
    const int tid = threadIdx.x;
    const int tx = tid & 15, ty = tid >> 4;
    const int brow = blockIdx.y * 128;
    const int bcol = blockIdx.x * 128;

    float acc[8][8];
#pragma unroll
    for (int i = 0; i < 8; i++)
#pragma unroll
        for (int j = 0; j < 8; j++) acc[i][j] = 0.f;

    const int ar = tid >> 1;           // A row within tile (0..127)
    const int ac = (tid & 1) * 4;      // A k-offset (0 or 4)
    const int br = tid >> 5;           // B k-row (0..7)
    const int bc = (tid & 31) * 4;     // B col offset (0..124)

    const float* Aptr = A + (size_t)(brow + ar) * K + ac;
    const float* Bptr = Bm + (size_t)br * N + bcol + bc;

    // Preload tile 0
    float4 av = *(const float4*)(Aptr);
    float4 bv = *(const float4*)(Bptr);
    As[0][ac + 0][ar] = av.x;
    As[0][ac + 1][ar] = av.y;
    As[0][ac + 2][ar] = av.z;
    As[0][ac + 3][ar] = av.w;
    *(float4*)&Bs[0][br][bc] = bv;
    __syncthreads();

    int buf = 0;
    for (int k0 = 0; k0 < K; k0 += 8) {
        const bool more = (k0 + 8) < K;
        if (more) {
            av = *(const float4*)(Aptr + k0 + 8);
            bv = *(const float4*)(Bptr + (size_t)(k0 + 8) * N);
        }
#pragma unroll
        for (int kk = 0; kk < 8; kk++) {
            float a[8], b[8];
            *(float4*)&a[0] = *(const float4*)&As[buf][kk][ty * 8];
            *(float4*)&a[4] = *(const float4*)&As[buf][kk][ty * 8 + 4];
            *(float4*)&b[0] = *(const float4*)&Bs[buf][kk][tx * 4];
            *(float4*)&b[4] = *(const float4*)&Bs[buf][kk][64 + tx * 4];
#pragma unroll
            for (int i = 0; i < 8; i++)
#pragma unroll
                for (int j = 0; j < 8; j++) acc[i][j] += a[i] * b[j];
        }
        if (more) {
            int nb = buf ^ 1;
            As[nb][ac + 0][ar] = av.x;
            As[nb][ac + 1][ar] = av.y;
            As[nb][ac + 2][ar] = av.z;
            As[nb][ac + 3][ar] = av.w;
            *(float4*)&Bs[nb][br][bc] = bv;
        }
        __syncthreads();
        buf ^= 1;
    }
#pragma unroll
    for (int i = 0; i < 8; i++) {
        float* crow = C + (size_t)(brow + ty * 8 + i) * N + bcol;
        float4 v0 = make_float4(acc[i][0], acc[i][1], acc[i][2], acc[i][3]);
        float4 v1 = make_float4(acc[i][4], acc[i][5], acc[i][6], acc[i][7]);
        *(float4*)(crow + tx * 4) = v0;
        *(float4*)(crow + 64 + tx * 4) = v1;
    }
}

// ---------------------------------------------------------------------------
// RoPE table: one entry per (bs, freq-index). Double precision angle (|angle|
// up to ~2047 rad), computed ONCE per entry instead of 9x per entry.
// ---------------------------------------------------------------------------
__global__ void rope_table_kernel(const int* __restrict__ pos_ids) {
    int idx = blockIdx.x * blockDim.x + threadIdx.x;
    if (idx >= MROWS * 128) return;
    int i = idx & 127;
    int bs = idx >> 7;
    // freq = 10000^(-i/128) = exp(-i * ln(10000)/128)
    double freq = exp(-(double)i * 0.07195578415606392);
    double ang = (double)pos_ids[bs] * freq;
    double sd, cd;
    sincos(ang, &sd, &cd);
    g_rope[idx] = make_float2((float)cd, (float)sd);
}

// RoPE apply: pure fp32, memory-bound.
__global__ void rope_apply_kernel() {
    int idx = blockIdx.x * blockDim.x + threadIdx.x;
    const int total = MROWS * 9 * 128;  // 8 q-heads + 1 k-head, 128 pairs each
    if (idx >= total) return;
    int i = idx & 127;
    int rest = idx >> 7;
    int h = rest % 9;
    int bs = rest / 9;

    float2 cs = g_rope[bs * 128 + i];
    float* base = (h < 8) ? (g_q + (size_t)bs * (NH * HDIM) + h * HDIM)
                          : (g_k + (size_t)bs * HDIM);
    float x0 = base[i];
    float x1 = base[i + 128];
    base[i]       = x0 * cs.x - x1 * cs.y;
    base[i + 128] = x1 * cs.x + x0 * cs.y;
}

// ---------------------------------------------------------------------------
// Flash attention (fp32, online softmax). One block = 64 queries for one
// (b, h). K/V shared across heads (MQA). 64-key tiles staged in smem.
// ---------------------------------------------------------------------------
#define FLASH_SMEM_FLOATS (2 * 64 * QKSTR + 64 * 65 + 3 * 64)
#define FLASH_SMEM_BYTES  (FLASH_SMEM_FLOATS * 4)

__global__ void __launch_bounds__(256)
flash_attn(const float* __restrict__ mask) {
    extern __shared__ float sm[];
    float* qs     = sm;                       // [64][257]
    float* kvs    = sm + 64 * QKSTR;          // [64][257] (K then reused for V)
    float* ps     = sm + 2 * 64 * QKSTR;      // [64][65]  exp'd probabilities
    float* m_s    = ps + 64 * 65;             // [64] running max
    float* l_s    = m_s + 64;                 // [64] running denom
    float* corr_s = l_s + 64;                 // [64] per-tile rescale

    const int tid = threadIdx.x;
    const int tx = tid & 15, ty = tid >> 4;
    const int q0 = blockIdx.x * 64;
    const int bh = blockIdx.y;
    const int b = bh >> 3, h = bh & 7;

    const float* qg = g_q + (size_t)(b * SEQ + q0) * (NH * HDIM) + h * HDIM;
    for (int t = tid; t < 64 * 64; t += 256) {
        int r = t >> 6;
        int c4 = (t & 63) * 4;
        float4 v = *(const float4*)(qg + (size_t)r * (NH * HDIM) + c4);
        float* dst = qs + r * QKSTR + c4;
        dst[0] = v.x; dst[1] = v.y; dst[2] = v.z; dst[3] = v.w;
    }
    if (tid < 64) { m_s[tid] = -1e30f; l_s[tid] = 0.f; }

    float o[4][16];
#pragma unroll
    for (int i = 0; i < 4; i++)
#pragma unroll
        for (int j = 0; j < 16; j++) o[i][j] = 0.f;
    __syncthreads();

    for (int k0 = 0; k0 < SEQ; k0 += 64) {
        const float* kg = g_k + (size_t)(b * SEQ + k0) * HDIM;
        for (int t = tid; t < 64 * 64; t += 256) {
            int r = t >> 6;
            int c4 = (t & 63) * 4;
            float4 v = *(const float4*)(kg + (size_t)r * HDIM + c4);
            float* dst = kvs + r * QKSTR + c4;
            dst[0] = v.x; dst[1] = v.y; dst[2] = v.z; dst[3] = v.w;
        }
        __syncthreads();

        float s[4][4];
#pragma unroll
        for (int i = 0; i < 4; i++)
#pragma unroll
            for (int j = 0; j < 4; j++) s[i][j] = 0.f;

        const float* qrow = qs + (ty * 4) * QKSTR;
        const float* krow = kvs + (tx * 4) * QKSTR;
#pragma unroll 8
        for (int d = 0; d < 256; d++) {
            float a0 = qrow[d];
            float a1 = qrow[QKSTR + d];
            float a2 = qrow[2 * QKSTR + d];
            float a3 = qrow[3 * QKSTR + d];
            float b0 = krow[d];
            float b1 = krow[QKSTR + d];
            float b2 = krow[2 * QKSTR + d];
            float b3 = krow[3 * QKSTR + d];
            s[0][0] += a0 * b0; s[0][1] += a0 * b1; s[0][2] += a0 * b2; s[0][3] += a0 * b3;
            s[1][0] += a1 * b0; s[1][1] += a1 * b1; s[1][2] += a1 * b2; s[1][3] += a1 * b3;
            s[2][0] += a2 * b0; s[2][1] += a2 * b1; s[2][2] += a2 * b2; s[2][3] += a2 * b3;
            s[3][0] += a3 * b0; s[3][1] += a3 * b1; s[3][2] += a3 * b2; s[3][3] += a3 * b3;
        }

        const float* mrow = mask + (size_t)b * SEQ * SEQ
                                 + (size_t)(q0 + ty * 4) * SEQ + (k0 + tx * 4);
#pragma unroll
        for (int i = 0; i < 4; i++) {
            int r = ty * 4 + i;
            float sv[4];
#pragma unroll
            for (int j = 0; j < 4; j++)
                sv[j] = s[i][j] * 0.0625f + mrow[(size_t)i * SEQ + j];
            float mx = fmaxf(fmaxf(sv[0], sv[1]), fmaxf(sv[2], sv[3]));
#pragma unroll
            for (int off = 8; off >= 1; off >>= 1)
                mx = fmaxf(mx, __shfl_xor_sync(0xffffffffu, mx, off, 16));
            float m_old = m_s[r];
            float m_new = fmaxf(m_old, mx);
            float sum = 0.f;
#pragma unroll
            for (int j = 0; j < 4; j++) {
                float p = __expf(sv[j] - m_new);
                ps[r * 65 + tx * 4 + j] = p;
                sum += p;
            }
#pragma unroll
            for (int off = 8; off >= 1; off >>= 1)
                sum += __shfl_xor_sync(0xffffffffu, sum, off, 16);
            if (tx == 0) {
                float corr = __expf(m_old - m_new);
                corr_s[r] = corr;
                l_s[r] = l_s[r] * corr + sum;
                m_s[r] = m_new;
            }
        }
        __syncthreads();

#pragma unroll
        for (int i = 0; i < 4; i++) {
            float corr = corr_s[ty * 4 + i];
#pragma unroll
            for (int j = 0; j < 16; j++) o[i][j] *= corr;
        }
        const float* vg = g_v + (size_t)(b * SEQ + k0) * HDIM;
        for (int t = tid; t < 64 * 64; t += 256) {
            int r = t >> 6;
            int c4 = (t & 63) * 4;
            float4 v = *(const float4*)(vg + (size_t)r * HDIM + c4);
            float* dst = kvs + r * QKSTR + c4;
            dst[0] = v.x; dst[1] = v.y; dst[2] = v.z; dst[3] = v.w;
        }
        __syncthreads();

        const float* psr = ps + (ty * 4) * 65;
        for (int kk = 0; kk < 64; kk++) {
            float p0 = psr[kk];
            float p1 = psr[65 + kk];
            float p2 = psr[130 + kk];
            float p3 = psr[195 + kk];
            const float* vr = kvs + kk * QKSTR + tx;
#pragma unroll
            for (int j = 0; j < 16; j++) {
                float vv = vr[16 * j];
                o[0][j] += p0 * vv;
                o[1][j] += p1 * vv;
                o[2][j] += p2 * vv;
                o[3][j] += p3 * vv;
            }
        }
        __syncthreads();
    }

#pragma unroll
    for (int i = 0; i < 4; i++) {
        int r = ty * 4 + i;
        float inv = 1.0f / l_s[r];
        float* og = g_ao + (size_t)(b * SEQ + q0 + r) * (NH * HDIM) + h * HDIM;
#pragma unroll
        for (int j = 0; j < 16; j++)
            og[tx + 16 * j] = o[i][j] * inv;
    }
}

// ---------------------------------------------------------------------------
extern "C" void kernel_launch(void* const* d_in, const int* in_sizes, int n_in,
                              void* d_out, int out_size) {
    const float* hidden = (const float*)d_in[0];
    const float* mask   = (const float*)d_in[1];
    const int*   pos    = (const int*)d_in[2];
    const float* Wq     = (const float*)d_in[3];
    const float* Wk     = (const float*)d_in[4];
    const float* Wv     = (const float*)d_in[5];
    const float* Wo     = (const float*)d_in[6];
    float* out = (float*)d_out;

    float *qb, *kb, *vb, *aob;
    cudaGetSymbolAddress((void**)&qb, g_q);
    cudaGetSymbolAddress((void**)&kb, g_k);
    cudaGetSymbolAddress((void**)&vb, g_v);
    cudaGetSymbolAddress((void**)&aob, g_ao);

    cudaFuncSetAttribute(flash_attn, cudaFuncAttributeMaxDynamicSharedMemorySize,
                         FLASH_SMEM_BYTES);

    // RoPE table overlaps nothing it depends on -> launch first (stream order
    // still serial, but it's cheap now).
    int ttot = MROWS * 128;
    rope_table_kernel<<<(ttot + 255) / 256, 256>>>(pos);

    // Q/K/V projections
    dim3 gq(DMODEL / 128, MROWS / 128);      // (16, 32)
    sgemm128<<<gq, 256>>>(hidden, Wq, qb, MROWS, NH * HDIM, DMODEL);
    dim3 gkv(HDIM / 128, MROWS / 128);       // (2, 32)
    sgemm128<<<gkv, 256>>>(hidden, Wk, kb, MROWS, HDIM, DMODEL);
    sgemm128<<<gkv, 256>>>(hidden, Wv, vb, MROWS, HDIM, DMODEL);

    // RoPE on q and k
    int rtot = MROWS * 9 * 128;
    rope_apply_kernel<<<(rtot + 255) / 256, 256>>>();

    // Fused attention
    dim3 gf(SEQ / 64, BATCH * NH);           // (32, 16)
    flash_attn<<<gf, 256, FLASH_SMEM_BYTES>>>(mask);

    // Output projection -> d_out
    sgemm128<<<gq, 256>>>(aob, Wo, out, MROWS, DMODEL, DMODEL);
}

// round 5
// speedup vs baseline: 1.6382x; 1.2641x over previous
#include <cuda_runtime.h>
#include <cuda_bf16.h>
#include <math.h>
#include <stdint.h>

#define BATCH 2
#define SEQ 2048
#define DMODEL 2048
#define NH 8
#define HDIM 256
#define MROWS (BATCH * SEQ)          // 4096
#define QKSTR 257

// ---------------- fp32 scratch ----------------
static __device__ float g_q[MROWS * NH * HDIM];
static __device__ float g_k[MROWS * HDIM];
static __device__ float g_v[MROWS * HDIM];
static __device__ float g_ao[MROWS * NH * HDIM];
static __device__ float2 g_rope[MROWS * 128];

// ---------------- bf16 split scratch ----------------
static __device__ __nv_bfloat16 g_hid_hi[MROWS * DMODEL];
static __device__ __nv_bfloat16 g_hid_lo[MROWS * DMODEL];
static __device__ __nv_bfloat16 g_ao_hi[MROWS * DMODEL];
static __device__ __nv_bfloat16 g_ao_lo[MROWS * DMODEL];
static __device__ __nv_bfloat16 g_wq_hi[DMODEL * DMODEL];   // [N][K] transposed
static __device__ __nv_bfloat16 g_wq_lo[DMODEL * DMODEL];
static __device__ __nv_bfloat16 g_wk_hi[HDIM * DMODEL];
static __device__ __nv_bfloat16 g_wk_lo[HDIM * DMODEL];
static __device__ __nv_bfloat16 g_wv_hi[HDIM * DMODEL];
static __device__ __nv_bfloat16 g_wv_lo[HDIM * DMODEL];
static __device__ __nv_bfloat16 g_wo_hi[DMODEL * DMODEL];
static __device__ __nv_bfloat16 g_wo_lo[DMODEL * DMODEL];

// ---------------------------------------------------------------------------
// Warp-MMA helpers (baseline PTX, works under compute_103)
// ---------------------------------------------------------------------------
__device__ __forceinline__ uint32_t smem_u32(const void* p) {
    uint32_t a;
    asm("{ .reg .u64 t; cvta.to.shared.u64 t, %1; cvt.u32.u64 %0, t; }"
        : "=r"(a) : "l"(p));
    return a;
}
__device__ __forceinline__ void cp16(uint32_t s, const void* g) {
    asm volatile("cp.async.ca.shared.global [%0], [%1], 16;" :: "r"(s), "l"(g));
}
__device__ __forceinline__ void cp_commit() {
    asm volatile("cp.async.commit_group;" ::: "memory");
}
__device__ __forceinline__ void ldsm4(uint32_t* r, uint32_t a) {
    asm volatile("ldmatrix.sync.aligned.m8n8.x4.shared.b16 {%0,%1,%2,%3}, [%4];"
                 : "=r"(r[0]), "=r"(r[1]), "=r"(r[2]), "=r"(r[3]) : "r"(a));
}
__device__ __forceinline__ void mma16816(float* c, const uint32_t* a, const uint32_t* b) {
    asm volatile(
        "mma.sync.aligned.m16n8k16.row.col.f32.bf16.bf16.f32 "
        "{%0,%1,%2,%3}, {%4,%5,%6,%7}, {%8,%9}, {%0,%1,%2,%3};"
        : "+f"(c[0]), "+f"(c[1]), "+f"(c[2]), "+f"(c[3])
        : "r"(a[0]), "r"(a[1]), "r"(a[2]), "r"(a[3]), "r"(b[0]), "r"(b[1]));
}

// ---------------------------------------------------------------------------
// mma_gemm: C[M,N] = (Ah+Al)[M,K] @ (Bh+Bl)^T, B stored [N][K] bf16.
// bf16x3: AhBh + AhBl + AlBh, fp32 accum. CTA tile 128x128, BK=32, 8 warps,
// warp tile 64x32. Smem rows: 32 bf16 data in 40-bf16 (80B) stride
// (ldmatrix conflict-free). cp.async double buffered.
// ---------------------------------------------------------------------------
#define RSB 40                            // bf16 row stride in smem
#define TILE_B (128 * RSB * 2)            // 10240 bytes per tile array
#define BUF_B (4 * TILE_B)                // AH AL BH BL
#define MMA_SMEM (2 * BUF_B)              // 81920 bytes

__global__ void __launch_bounds__(256, 1)
mma_gemm(const __nv_bfloat16* __restrict__ Ah, const __nv_bfloat16* __restrict__ Al,
         const __nv_bfloat16* __restrict__ Bh, const __nv_bfloat16* __restrict__ Bl,
         float* __restrict__ C, int M, int N, int Kd) {
    extern __shared__ char smg[];
    const uint32_t sb = smem_u32(smg);
    const int tid = threadIdx.x, wid = tid >> 5, lane = tid & 31;
    const int warp_m = wid >> 2, warp_n = wid & 3;   // 2 x 4 warps
    const int brow = blockIdx.y * 128, bcol = blockIdx.x * 128;

    float acc[4][4][4];
#pragma unroll
    for (int i = 0; i < 4; i++)
#pragma unroll
        for (int j = 0; j < 4; j++)
#pragma unroll
            for (int r = 0; r < 4; r++) acc[i][j][r] = 0.f;

    const int KT = Kd / 32;

    // g2s loader: 512 16B segments per tile array; thread does 2 per array.
    auto load_tile = [&](int kt, int buf) {
        const int k0 = kt * 32;
        const uint32_t bo = sb + buf * BUF_B;
#pragma unroll
        for (int s = tid; s < 512; s += 256) {
            const int row = s >> 2, seg = s & 3;
            const uint32_t so = (uint32_t)(row * 80 + seg * 16);
            const size_t ga = (size_t)(brow + row) * Kd + k0 + seg * 8;
            const size_t gb = (size_t)(bcol + row) * Kd + k0 + seg * 8;
            cp16(bo + so,              Ah + ga);
            cp16(bo + TILE_B + so,     Al + ga);
            cp16(bo + 2 * TILE_B + so, Bh + gb);
            cp16(bo + 3 * TILE_B + so, Bl + gb);
        }
        cp_commit();
    };

    load_tile(0, 0);

    for (int kt = 0; kt < KT; kt++) {
        const int cur = kt & 1;
        if (kt + 1 < KT) {
            load_tile(kt + 1, cur ^ 1);
            asm volatile("cp.async.wait_group 1;" ::: "memory");
        } else {
            asm volatile("cp.async.wait_group 0;" ::: "memory");
        }
        __syncthreads();

        const uint32_t sA = sb + cur * BUF_B;
        const uint32_t sB = sA + 2 * TILE_B;
#pragma unroll
        for (int ks = 0; ks < 2; ks++) {
            uint32_t ah[4][4], al[4][4], bh[4][2], bl[4][2];
#pragma unroll
            for (int mt = 0; mt < 4; mt++) {
                uint32_t addr = sA + (uint32_t)((warp_m * 64 + mt * 16 + (lane & 15)) * 80
                                                + (ks * 16 + (lane >> 4) * 8) * 2);
                ldsm4(ah[mt], addr);
                ldsm4(al[mt], addr + TILE_B);
            }
#pragma unroll
            for (int p = 0; p < 2; p++) {
                uint32_t addr = sB + (uint32_t)((warp_n * 32 + p * 16 + (lane & 15)) * 80
                                                + ks * 32 + (lane >> 4) * 16);
                uint32_t r[4], q[4];
                ldsm4(r, addr);
                ldsm4(q, addr + TILE_B);
                bh[2 * p][0] = r[0]; bh[2 * p][1] = r[2];
                bh[2 * p + 1][0] = r[1]; bh[2 * p + 1][1] = r[3];
                bl[2 * p][0] = q[0]; bl[2 * p][1] = q[2];
                bl[2 * p + 1][0] = q[1]; bl[2 * p + 1][1] = q[3];
            }
#pragma unroll
            for (int mt = 0; mt < 4; mt++)
#pragma unroll
                for (int nt = 0; nt < 4; nt++) {
                    mma16816(acc[mt][nt], ah[mt], bh[nt]);
                    mma16816(acc[mt][nt], ah[mt], bl[nt]);
                    mma16816(acc[mt][nt], al[mt], bh[nt]);
                }
        }
        __syncthreads();
    }

    // epilogue: c0,c1 -> (row lane/4, col (lane&3)*2); c2,c3 -> row+8
#pragma unroll
    for (int mt = 0; mt < 4; mt++) {
#pragma unroll
        for (int nt = 0; nt < 4; nt++) {
            const int row0 = brow + warp_m * 64 + mt * 16 + (lane >> 2);
            const int col = bcol + warp_n * 32 + nt * 8 + (lane & 3) * 2;
            *(float2*)(C + (size_t)row0 * N + col) =
                make_float2(acc[mt][nt][0], acc[mt][nt][1]);
            *(float2*)(C + (size_t)(row0 + 8) * N + col) =
                make_float2(acc[mt][nt][2], acc[mt][nt][3]);
        }
    }
}

// ---------------------------------------------------------------------------
// bf16 hi/lo splits
// ---------------------------------------------------------------------------
__global__ void split_bf16(const float* __restrict__ src,
                           __nv_bfloat16* __restrict__ hi,
                           __nv_bfloat16* __restrict__ lo, int n) {
    int i = blockIdx.x * blockDim.x + threadIdx.x;
    if (i >= n) return;
    float x = src[i];
    __nv_bfloat16 h = __float2bfloat16(x);
    hi[i] = h;
    lo[i] = __float2bfloat16(x - __bfloat162float(h));
}

__global__ void split_bf16_T(const float* __restrict__ W,
                             __nv_bfloat16* __restrict__ hi,
                             __nv_bfloat16* __restrict__ lo, int K, int N) {
    __shared__ float tile[32][33];
    int k0 = blockIdx.y * 32, n0 = blockIdx.x * 32;
    int tx = threadIdx.x, ty = threadIdx.y;  // 32 x 8
#pragma unroll
    for (int i = 0; i < 32; i += 8)
        tile[ty + i][tx] = W[(size_t)(k0 + ty + i) * N + n0 + tx];
    __syncthreads();
#pragma unroll
    for (int i = 0; i < 32; i += 8) {
        float x = tile[tx][ty + i];
        __nv_bfloat16 h = __float2bfloat16(x);
        size_t o = (size_t)(n0 + ty + i) * K + k0 + tx;
        hi[o] = h;
        lo[o] = __float2bfloat16(x - __bfloat162float(h));
    }
}

// ---------------------------------------------------------------------------
// RoPE table + apply
// ---------------------------------------------------------------------------
__global__ void rope_table_kernel(const int* __restrict__ pos_ids) {
    int idx = blockIdx.x * blockDim.x + threadIdx.x;
    if (idx >= MROWS * 128) return;
    int i = idx & 127;
    int bs = idx >> 7;
    double freq = exp(-(double)i * 0.07195578415606392);
    double ang = (double)pos_ids[bs] * freq;
    double sd, cd;
    sincos(ang, &sd, &cd);
    g_rope[idx] = make_float2((float)cd, (float)sd);
}

__global__ void rope_apply_kernel() {
    int idx = blockIdx.x * blockDim.x + threadIdx.x;
    const int total = MROWS * 9 * 128;
    if (idx >= total) return;
    int i = idx & 127;
    int rest = idx >> 7;
    int h = rest % 9;
    int bs = rest / 9;
    float2 cs = g_rope[bs * 128 + i];
    float* base = (h < 8) ? (g_q + (size_t)bs * (NH * HDIM) + h * HDIM)
                          : (g_k + (size_t)bs * HDIM);
    float x0 = base[i];
    float x1 = base[i + 128];
    base[i]       = x0 * cs.x - x1 * cs.y;
    base[i + 128] = x1 * cs.x + x0 * cs.y;
}

// ---------------------------------------------------------------------------
// Flash attention (fp32 SIMT)
// ---------------------------------------------------------------------------
#define FLASH_SMEM_FLOATS (2 * 64 * QKSTR + 64 * 65 + 3 * 64)
#define FLASH_SMEM_BYTES  (FLASH_SMEM_FLOATS * 4)

__global__ void __launch_bounds__(256)
flash_attn(const float* __restrict__ mask) {
    extern __shared__ float smf[];
    float* qs     = smf;
    float* kvs    = smf + 64 * QKSTR;
    float* ps     = smf + 2 * 64 * QKSTR;
    float* m_s    = ps + 64 * 65;
    float* l_s    = m_s + 64;
    float* corr_s = l_s + 64;

    const int tid = threadIdx.x;
    const int tx = tid & 15, ty = tid >> 4;
    const int q0 = blockIdx.x * 64;
    const int bh = blockIdx.y;
    const int b = bh >> 3, h = bh & 7;

    const float* qg = g_q + (size_t)(b * SEQ + q0) * (NH * HDIM) + h * HDIM;
    for (int t = tid; t < 64 * 64; t += 256) {
        int r = t >> 6;
        int c4 = (t & 63) * 4;
        float4 v = *(const float4*)(qg + (size_t)r * (NH * HDIM) + c4);
        float* dst = qs + r * QKSTR + c4;
        dst[0] = v.x; dst[1] = v.y; dst[2] = v.z; dst[3] = v.w;
    }
    if (tid < 64) { m_s[tid] = -1e30f; l_s[tid] = 0.f; }

    float o[4][16];
#pragma unroll
    for (int i = 0; i < 4; i++)
#pragma unroll
        for (int j = 0; j < 16; j++) o[i][j] = 0.f;
    __syncthreads();

    for (int k0 = 0; k0 < SEQ; k0 += 64) {
        const float* kg = g_k + (size_t)(b * SEQ + k0) * HDIM;
        for (int t = tid; t < 64 * 64; t += 256) {
            int r = t >> 6;
            int c4 = (t & 63) * 4;
            float4 v = *(const float4*)(kg + (size_t)r * HDIM + c4);
            float* dst = kvs + r * QKSTR + c4;
            dst[0] = v.x; dst[1] = v.y; dst[2] = v.z; dst[3] = v.w;
        }
        __syncthreads();

        float s[4][4];
#pragma unroll
        for (int i = 0; i < 4; i++)
#pragma unroll
            for (int j = 0; j < 4; j++) s[i][j] = 0.f;

        const float* qrow = qs + (ty * 4) * QKSTR;
        const float* krow = kvs + (tx * 4) * QKSTR;
#pragma unroll 8
        for (int d = 0; d < 256; d++) {
            float a0 = qrow[d];
            float a1 = qrow[QKSTR + d];
            float a2 = qrow[2 * QKSTR + d];
            float a3 = qrow[3 * QKSTR + d];
            float b0 = krow[d];
            float b1 = krow[QKSTR + d];
            float b2 = krow[2 * QKSTR + d];
            float b3 = krow[3 * QKSTR + d];
            s[0][0] += a0 * b0; s[0][1] += a0 * b1; s[0][2] += a0 * b2; s[0][3] += a0 * b3;
            s[1][0] += a1 * b0; s[1][1] += a1 * b1; s[1][2] += a1 * b2; s[1][3] += a1 * b3;
            s[2][0] += a2 * b0; s[2][1] += a2 * b1; s[2][2] += a2 * b2; s[2][3] += a2 * b3;
            s[3][0] += a3 * b0; s[3][1] += a3 * b1; s[3][2] += a3 * b2; s[3][3] += a3 * b3;
        }

        const float* mrow = mask + (size_t)b * SEQ * SEQ
                                 + (size_t)(q0 + ty * 4) * SEQ + (k0 + tx * 4);
#pragma unroll
        for (int i = 0; i < 4; i++) {
            int r = ty * 4 + i;
            float sv[4];
#pragma unroll
            for (int j = 0; j < 4; j++)
                sv[j] = s[i][j] * 0.0625f + mrow[(size_t)i * SEQ + j];
            float mx = fmaxf(fmaxf(sv[0], sv[1]), fmaxf(sv[2], sv[3]));
#pragma unroll
            for (int off = 8; off >= 1; off >>= 1)
                mx = fmaxf(mx, __shfl_xor_sync(0xffffffffu, mx, off, 16));
            float m_old = m_s[r];
            float m_new = fmaxf(m_old, mx);
            float sum = 0.f;
#pragma unroll
            for (int j = 0; j < 4; j++) {
                float p = __expf(sv[j] - m_new);
                ps[r * 65 + tx * 4 + j] = p;
                sum += p;
            }
#pragma unroll
            for (int off = 8; off >= 1; off >>= 1)
                sum += __shfl_xor_sync(0xffffffffu, sum, off, 16);
            if (tx == 0) {
                float corr = __expf(m_old - m_new);
                corr_s[r] = corr;
                l_s[r] = l_s[r] * corr + sum;
                m_s[r] = m_new;
            }
        }
        __syncthreads();

#pragma unroll
        for (int i = 0; i < 4; i++) {
            float corr = corr_s[ty * 4 + i];
#pragma unroll
            for (int j = 0; j < 16; j++) o[i][j] *= corr;
        }
        const float* vg = g_v + (size_t)(b * SEQ + k0) * HDIM;
        for (int t = tid; t < 64 * 64; t += 256) {
            int r = t >> 6;
            int c4 = (t & 63) * 4;
            float4 v = *(const float4*)(vg + (size_t)r * HDIM + c4);
            float* dst = kvs + r * QKSTR + c4;
            dst[0] = v.x; dst[1] = v.y; dst[2] = v.z; dst[3] = v.w;
        }
        __syncthreads();

        const float* psr = ps + (ty * 4) * 65;
        for (int kk = 0; kk < 64; kk++) {
            float p0 = psr[kk];
            float p1 = psr[65 + kk];
            float p2 = psr[130 + kk];
            float p3 = psr[195 + kk];
            const float* vr = kvs + kk * QKSTR + tx;
#pragma unroll
            for (int j = 0; j < 16; j++) {
                float vv = vr[16 * j];
                o[0][j] += p0 * vv;
                o[1][j] += p1 * vv;
                o[2][j] += p2 * vv;
                o[3][j] += p3 * vv;
            }
        }
        __syncthreads();
    }

#pragma unroll
    for (int i = 0; i < 4; i++) {
        int r = ty * 4 + i;
        float inv = 1.0f / l_s[r];
        float* og = g_ao + (size_t)(b * SEQ + q0 + r) * (NH * HDIM) + h * HDIM;
#pragma unroll
        for (int j = 0; j < 16; j++)
            og[tx + 16 * j] = o[i][j] * inv;
    }
}

// ---------------------------------------------------------------------------
extern "C" void kernel_launch(void* const* d_in, const int* in_sizes, int n_in,
                              void* d_out, int out_size) {
    const float* hidden = (const float*)d_in[0];
    const float* mask   = (const float*)d_in[1];
    const int*   pos    = (const int*)d_in[2];
    const float* Wq     = (const float*)d_in[3];
    const float* Wk     = (const float*)d_in[4];
    const float* Wv     = (const float*)d_in[5];
    const float* Wo     = (const float*)d_in[6];
    float* out = (float*)d_out;

    float *qb, *kb, *vb, *aob;
    cudaGetSymbolAddress((void**)&qb, g_q);
    cudaGetSymbolAddress((void**)&kb, g_k);
    cudaGetSymbolAddress((void**)&vb, g_v);
    cudaGetSymbolAddress((void**)&aob, g_ao);
    __nv_bfloat16 *hh, *hl, *aoh, *aol, *qh, *ql, *kh, *kl, *vh, *vl, *oh, *ol;
    cudaGetSymbolAddress((void**)&hh, g_hid_hi);
    cudaGetSymbolAddress((void**)&hl, g_hid_lo);
    cudaGetSymbolAddress((void**)&aoh, g_ao_hi);
    cudaGetSymbolAddress((void**)&aol, g_ao_lo);
    cudaGetSymbolAddress((void**)&qh, g_wq_hi);
    cudaGetSymbolAddress((void**)&ql, g_wq_lo);
    cudaGetSymbolAddress((void**)&kh, g_wk_hi);
    cudaGetSymbolAddress((void**)&kl, g_wk_lo);
    cudaGetSymbolAddress((void**)&vh, g_wv_hi);
    cudaGetSymbolAddress((void**)&vl, g_wv_lo);
    cudaGetSymbolAddress((void**)&oh, g_wo_hi);
    cudaGetSymbolAddress((void**)&ol, g_wo_lo);

    cudaFuncSetAttribute(flash_attn, cudaFuncAttributeMaxDynamicSharedMemorySize,
                         FLASH_SMEM_BYTES);
    cudaFuncSetAttribute(mma_gemm, cudaFuncAttributeMaxDynamicSharedMemorySize,
                         MMA_SMEM);

    // RoPE table (independent)
    int ttot = MROWS * 128;
    rope_table_kernel<<<(ttot + 255) / 256, 256>>>(pos);

    // Splits: hidden (row-major) + weights (transposed to [N][K])
    int nh = MROWS * DMODEL;
    split_bf16<<<(nh + 255) / 256, 256>>>(hidden, hh, hl, nh);
    dim3 tb(32, 8);
    split_bf16_T<<<dim3(DMODEL / 32, DMODEL / 32), tb>>>(Wq, qh, ql, DMODEL, DMODEL);
    split_bf16_T<<<dim3(HDIM / 32, DMODEL / 32), tb>>>(Wk, kh, kl, DMODEL, HDIM);
    split_bf16_T<<<dim3(HDIM / 32, DMODEL / 32), tb>>>(Wv, vh, vl, DMODEL, HDIM);
    split_bf16_T<<<dim3(DMODEL / 32, DMODEL / 32), tb>>>(Wo, oh, ol, DMODEL, DMODEL);

    // Projections on tensor cores (HMMA)
    mma_gemm<<<dim3(DMODEL / 128, MROWS / 128), 256, MMA_SMEM>>>(
        hh, hl, qh, ql, qb, MROWS, DMODEL, DMODEL);
    mma_gemm<<<dim3(HDIM / 128, MROWS / 128), 256, MMA_SMEM>>>(
        hh, hl, kh, kl, kb, MROWS, HDIM, DMODEL);
    mma_gemm<<<dim3(HDIM / 128, MROWS / 128), 256, MMA_SMEM>>>(
        hh, hl, vh, vl, vb, MROWS, HDIM, DMODEL);

    // RoPE
    int rtot = MROWS * 9 * 128;
    rope_apply_kernel<<<(rtot + 255) / 256, 256>>>();

    // Attention
    dim3 gf(SEQ / 64, BATCH * NH);
    flash_attn<<<gf, 256, FLASH_SMEM_BYTES>>>(mask);

    // Output projection
    split_bf16<<<(nh + 255) / 256, 256>>>(aob, aoh, aol, nh);
    mma_gemm<<<dim3(DMODEL / 128, MROWS / 128), 256, MMA_SMEM>>>(
        aoh, aol, oh, ol, out, MROWS, DMODEL, DMODEL);
}

// round 6
// speedup vs baseline: 2.9196x; 1.7821x over previous
#include <cuda_runtime.h>
#include <cuda_bf16.h>
#include <math.h>
#include <stdint.h>

#define BATCH 2
#define SEQ 2048
#define DMODEL 2048
#define NH 8
#define HDIM 256
#define MROWS (BATCH * SEQ)          // 4096

// ---------------- fp32 scratch ----------------
static __device__ float g_q[MROWS * NH * HDIM];
static __device__ float g_k[MROWS * HDIM];
static __device__ float g_v[MROWS * HDIM];
static __device__ float g_ao[MROWS * NH * HDIM];
static __device__ float2 g_rope[MROWS * 128];

// ---------------- bf16 split scratch ----------------
static __device__ __nv_bfloat16 g_hid_hi[MROWS * DMODEL];
static __device__ __nv_bfloat16 g_hid_lo[MROWS * DMODEL];
static __device__ __nv_bfloat16 g_ao_hi[MROWS * DMODEL];
static __device__ __nv_bfloat16 g_ao_lo[MROWS * DMODEL];
static __device__ __nv_bfloat16 g_wq_hi[DMODEL * DMODEL];
static __device__ __nv_bfloat16 g_wq_lo[DMODEL * DMODEL];
static __device__ __nv_bfloat16 g_wk_hi[HDIM * DMODEL];
static __device__ __nv_bfloat16 g_wk_lo[HDIM * DMODEL];
static __device__ __nv_bfloat16 g_wv_hi[HDIM * DMODEL];
static __device__ __nv_bfloat16 g_wv_lo[HDIM * DMODEL];
static __device__ __nv_bfloat16 g_wo_hi[DMODEL * DMODEL];
static __device__ __nv_bfloat16 g_wo_lo[DMODEL * DMODEL];
// flash attention operands (bf16 hi/lo, post-RoPE)
static __device__ __nv_bfloat16 g_qhi[MROWS * NH * HDIM];
static __device__ __nv_bfloat16 g_qlo[MROWS * NH * HDIM];
static __device__ __nv_bfloat16 g_khi[MROWS * HDIM];
static __device__ __nv_bfloat16 g_klo[MROWS * HDIM];
static __device__ __nv_bfloat16 g_vhi[MROWS * HDIM];
static __device__ __nv_bfloat16 g_vlo[MROWS * HDIM];

// ---------------------------------------------------------------------------
// Warp-MMA helpers (baseline PTX, works under compute_103)
// ---------------------------------------------------------------------------
__device__ __forceinline__ uint32_t smem_u32(const void* p) {
    uint32_t a;
    asm("{ .reg .u64 t; cvta.to.shared.u64 t, %1; cvt.u32.u64 %0, t; }"
        : "=r"(a) : "l"(p));
    return a;
}
__device__ __forceinline__ void cp16(uint32_t s, const void* g) {
    asm volatile("cp.async.ca.shared.global [%0], [%1], 16;" :: "r"(s), "l"(g));
}
__device__ __forceinline__ void cp_commit() {
    asm volatile("cp.async.commit_group;" ::: "memory");
}
__device__ __forceinline__ void ldsm4(uint32_t* r, uint32_t a) {
    asm volatile("ldmatrix.sync.aligned.m8n8.x4.shared.b16 {%0,%1,%2,%3}, [%4];"
                 : "=r"(r[0]), "=r"(r[1]), "=r"(r[2]), "=r"(r[3]) : "r"(a));
}
__device__ __forceinline__ void ldsm4t(uint32_t* r, uint32_t a) {
    asm volatile("ldmatrix.sync.aligned.m8n8.x4.trans.shared.b16 {%0,%1,%2,%3}, [%4];"
                 : "=r"(r[0]), "=r"(r[1]), "=r"(r[2]), "=r"(r[3]) : "r"(a));
}
__device__ __forceinline__ void mma16816(float* c, const uint32_t* a, const uint32_t* b) {
    asm volatile(
        "mma.sync.aligned.m16n8k16.row.col.f32.bf16.bf16.f32 "
        "{%0,%1,%2,%3}, {%4,%5,%6,%7}, {%8,%9}, {%0,%1,%2,%3};"
        : "+f"(c[0]), "+f"(c[1]), "+f"(c[2]), "+f"(c[3])
        : "r"(a[0]), "r"(a[1]), "r"(a[2]), "r"(a[3]), "r"(b[0]), "r"(b[1]));
}

// ---------------------------------------------------------------------------
// mma_gemm: C[M,N] = (Ah+Al)[M,K] @ (Bh+Bl)^T, B stored [N][K] bf16. (round-5)
// ---------------------------------------------------------------------------
#define RSB 40
#define TILE_B (128 * RSB * 2)
#define BUF_B (4 * TILE_B)
#define MMA_SMEM (2 * BUF_B)

__global__ void __launch_bounds__(256, 1)
mma_gemm(const __nv_bfloat16* __restrict__ Ah, const __nv_bfloat16* __restrict__ Al,
         const __nv_bfloat16* __restrict__ Bh, const __nv_bfloat16* __restrict__ Bl,
         float* __restrict__ C, int M, int N, int Kd) {
    extern __shared__ char smg[];
    const uint32_t sb = smem_u32(smg);
    const int tid = threadIdx.x, wid = tid >> 5, lane = tid & 31;
    const int warp_m = wid >> 2, warp_n = wid & 3;
    const int brow = blockIdx.y * 128, bcol = blockIdx.x * 128;

    float acc[4][4][4];
#pragma unroll
    for (int i = 0; i < 4; i++)
#pragma unroll
        for (int j = 0; j < 4; j++)
#pragma unroll
            for (int r = 0; r < 4; r++) acc[i][j][r] = 0.f;

    const int KT = Kd / 32;

    auto load_tile = [&](int kt, int buf) {
        const int k0 = kt * 32;
        const uint32_t bo = sb + buf * BUF_B;
#pragma unroll
        for (int s = tid; s < 512; s += 256) {
            const int row = s >> 2, seg = s & 3;
            const uint32_t so = (uint32_t)(row * 80 + seg * 16);
            const size_t ga = (size_t)(brow + row) * Kd + k0 + seg * 8;
            const size_t gb = (size_t)(bcol + row) * Kd + k0 + seg * 8;
            cp16(bo + so,              Ah + ga);
            cp16(bo + TILE_B + so,     Al + ga);
            cp16(bo + 2 * TILE_B + so, Bh + gb);
            cp16(bo + 3 * TILE_B + so, Bl + gb);
        }
        cp_commit();
    };

    load_tile(0, 0);

    for (int kt = 0; kt < KT; kt++) {
        const int cur = kt & 1;
        if (kt + 1 < KT) {
            load_tile(kt + 1, cur ^ 1);
            asm volatile("cp.async.wait_group 1;" ::: "memory");
        } else {
            asm volatile("cp.async.wait_group 0;" ::: "memory");
        }
        __syncthreads();

        const uint32_t sA = sb + cur * BUF_B;
        const uint32_t sB = sA + 2 * TILE_B;
#pragma unroll
        for (int ks = 0; ks < 2; ks++) {
            uint32_t ah[4][4], al[4][4], bh[4][2], bl[4][2];
#pragma unroll
            for (int mt = 0; mt < 4; mt++) {
                uint32_t addr = sA + (uint32_t)((warp_m * 64 + mt * 16 + (lane & 15)) * 80
                                                + (ks * 16 + (lane >> 4) * 8) * 2);
                ldsm4(ah[mt], addr);
                ldsm4(al[mt], addr + TILE_B);
            }
#pragma unroll
            for (int p = 0; p < 2; p++) {
                uint32_t addr = sB + (uint32_t)((warp_n * 32 + p * 16 + (lane & 15)) * 80
                                                + ks * 32 + (lane >> 4) * 16);
                uint32_t r[4], q[4];
                ldsm4(r, addr);
                ldsm4(q, addr + TILE_B);
                bh[2 * p][0] = r[0]; bh[2 * p][1] = r[2];
                bh[2 * p + 1][0] = r[1]; bh[2 * p + 1][1] = r[3];
                bl[2 * p][0] = q[0]; bl[2 * p][1] = q[2];
                bl[2 * p + 1][0] = q[1]; bl[2 * p + 1][1] = q[3];
            }
#pragma unroll
            for (int mt = 0; mt < 4; mt++)
#pragma unroll
                for (int nt = 0; nt < 4; nt++) {
                    mma16816(acc[mt][nt], ah[mt], bh[nt]);
                    mma16816(acc[mt][nt], ah[mt], bl[nt]);
                    mma16816(acc[mt][nt], al[mt], bh[nt]);
                }
        }
        __syncthreads();
    }

#pragma unroll
    for (int mt = 0; mt < 4; mt++) {
#pragma unroll
        for (int nt = 0; nt < 4; nt++) {
            const int row0 = brow + warp_m * 64 + mt * 16 + (lane >> 2);
            const int col = bcol + warp_n * 32 + nt * 8 + (lane & 3) * 2;
            *(float2*)(C + (size_t)row0 * N + col) =
                make_float2(acc[mt][nt][0], acc[mt][nt][1]);
            *(float2*)(C + (size_t)(row0 + 8) * N + col) =
                make_float2(acc[mt][nt][2], acc[mt][nt][3]);
        }
    }
}

// ---------------------------------------------------------------------------
// bf16 hi/lo splits
// ---------------------------------------------------------------------------
__global__ void split_bf16(const float* __restrict__ src,
                           __nv_bfloat16* __restrict__ hi,
                           __nv_bfloat16* __restrict__ lo, int n) {
    int i = blockIdx.x * blockDim.x + threadIdx.x;
    if (i >= n) return;
    float x = src[i];
    __nv_bfloat16 h = __float2bfloat16(x);
    hi[i] = h;
    lo[i] = __float2bfloat16(x - __bfloat162float(h));
}

__global__ void split_bf16_T(const float* __restrict__ W,
                             __nv_bfloat16* __restrict__ hi,
                             __nv_bfloat16* __restrict__ lo, int K, int N) {
    __shared__ float tile[32][33];
    int k0 = blockIdx.y * 32, n0 = blockIdx.x * 32;
    int tx = threadIdx.x, ty = threadIdx.y;
#pragma unroll
    for (int i = 0; i < 32; i += 8)
        tile[ty + i][tx] = W[(size_t)(k0 + ty + i) * N + n0 + tx];
    __syncthreads();
#pragma unroll
    for (int i = 0; i < 32; i += 8) {
        float x = tile[tx][ty + i];
        __nv_bfloat16 h = __float2bfloat16(x);
        size_t o = (size_t)(n0 + ty + i) * K + k0 + tx;
        hi[o] = h;
        lo[o] = __float2bfloat16(x - __bfloat162float(h));
    }
}

// ---------------------------------------------------------------------------
// RoPE table; RoPE apply fused with bf16 hi/lo split of q and k
// ---------------------------------------------------------------------------
__global__ void rope_table_kernel(const int* __restrict__ pos_ids) {
    int idx = blockIdx.x * blockDim.x + threadIdx.x;
    if (idx >= MROWS * 128) return;
    int i = idx & 127;
    int bs = idx >> 7;
    double freq = exp(-(double)i * 0.07195578415606392);
    double ang = (double)pos_ids[bs] * freq;
    double sd, cd;
    sincos(ang, &sd, &cd);
    g_rope[idx] = make_float2((float)cd, (float)sd);
}

__global__ void rope_apply_split() {
    int idx = blockIdx.x * blockDim.x + threadIdx.x;
    const int total = MROWS * 9 * 128;
    if (idx >= total) return;
    int i = idx & 127;
    int rest = idx >> 7;
    int h = rest % 9;
    int bs = rest / 9;
    float2 cs = g_rope[bs * 128 + i];

    const float* base;
    __nv_bfloat16 *dhi, *dlo;
    size_t o;
    if (h < 8) {
        o = (size_t)bs * (NH * HDIM) + h * HDIM;
        base = g_q + o;
        dhi = g_qhi; dlo = g_qlo;
    } else {
        o = (size_t)bs * HDIM;
        base = g_k + o;
        dhi = g_khi; dlo = g_klo;
    }
    float x0 = base[i], x1 = base[i + 128];
    float y0 = x0 * cs.x - x1 * cs.y;
    float y1 = x1 * cs.x + x0 * cs.y;
    __nv_bfloat16 h0 = __float2bfloat16(y0);
    __nv_bfloat16 h1 = __float2bfloat16(y1);
    dhi[o + i] = h0;
    dlo[o + i] = __float2bfloat16(y0 - __bfloat162float(h0));
    dhi[o + i + 128] = h1;
    dlo[o + i + 128] = __float2bfloat16(y1 - __bfloat162float(h1));
}

// ---------------------------------------------------------------------------
// Tensor-core flash attention. CTA = 64 queries for one (b,h); 8 warps.
// Scores: bf16x3 QK^T via HMMA, fp32 staged in smem; softmax fp32;
// PV: bf16x3 with P split at exp time, V B-fragments via ldmatrix.trans.
// ---------------------------------------------------------------------------
#define QS   264     // bf16 row stride for Q/K/V tiles (528B, conflict-free)
#define SSTR 66      // fp32 row stride for S
#define PSTR 72      // bf16 row stride for P (144B, conflict-free)

#define O_QHI  0
#define O_QLO  33792
#define O_KHI  67584
#define O_KLO  101376
#define O_S    135168
#define O_PHI  152064
#define O_PLO  161280
#define O_M    170496
#define O_L    170752
#define O_CORR 171008
#define FLASH_TC_SMEM 171264

__global__ void __launch_bounds__(256, 1)
flash_attn_tc(const float* __restrict__ mask) {
    extern __shared__ char smf[];
    const uint32_t sb = smem_u32(smf);
    const int tid = threadIdx.x, wid = tid >> 5, lane = tid & 31;
    const int q0 = blockIdx.x * 64;
    const int b = blockIdx.y >> 3, h = blockIdx.y & 7;

    float* S      = (float*)(smf + O_S);
    float* m_s    = (float*)(smf + O_M);
    float* l_s    = (float*)(smf + O_L);
    float* corr_s = (float*)(smf + O_CORR);

    // scores warp coords: 4 q-groups x 2 k-groups
    const int sqm = wid & 3, skn = wid >> 2;
    // PV warp coords: 2 q-groups x 4 d-groups
    const int pm = wid >> 2, pn = wid & 3;

    // ---- load Q tile (hi/lo) ----
    {
        const __nv_bfloat16* qh = g_qhi + (size_t)(b * SEQ + q0) * (NH * HDIM) + h * HDIM;
        const __nv_bfloat16* ql = g_qlo + (size_t)(b * SEQ + q0) * (NH * HDIM) + h * HDIM;
        for (int s = tid; s < 64 * 32; s += 256) {
            int r = s >> 5, c = (s & 31) * 8;
            uint32_t d = (uint32_t)(r * QS + c) * 2;
            *(uint4*)(smf + O_QHI + d) = *(const uint4*)(qh + (size_t)r * (NH * HDIM) + c);
            *(uint4*)(smf + O_QLO + d) = *(const uint4*)(ql + (size_t)r * (NH * HDIM) + c);
        }
    }
    if (tid < 64) { m_s[tid] = -1e30f; l_s[tid] = 0.f; }

    float acc[2][8][4];
#pragma unroll
    for (int i = 0; i < 2; i++)
#pragma unroll
        for (int j = 0; j < 8; j++)
#pragma unroll
            for (int r = 0; r < 4; r++) acc[i][j][r] = 0.f;

    __syncthreads();

    const uint32_t aBase = sb + O_QHI + (uint32_t)((sqm * 16 + (lane & 15)) * QS) * 2
                           + (lane >> 4) * 16;
    const uint32_t bBase = sb + O_KHI + (uint32_t)((skn * 32 + (lane & 15)) * QS) * 2
                           + (lane >> 4) * 16;
    const uint32_t pBase = sb + O_PHI + (uint32_t)((pm * 32 + (lane & 15)) * PSTR) * 2
                           + (lane >> 4) * 16;
    const uint32_t vBase = sb + O_KHI + (uint32_t)((lane & 15) * QS) * 2
                           + (uint32_t)(pn * 64 + (lane >> 4) * 8) * 2;

    for (int kt = 0; kt < 32; kt++) {
        const int k0 = kt * 64;

        // ---- load K tile (hi/lo) ----
        {
            const __nv_bfloat16* kh = g_khi + (size_t)(b * SEQ + k0) * HDIM;
            const __nv_bfloat16* kl = g_klo + (size_t)(b * SEQ + k0) * HDIM;
            for (int s = tid; s < 64 * 32; s += 256) {
                int r = s >> 5, c = (s & 31) * 8;
                uint32_t d = (uint32_t)(r * QS + c) * 2;
                *(uint4*)(smf + O_KHI + d) = *(const uint4*)(kh + (size_t)r * HDIM + c);
                *(uint4*)(smf + O_KLO + d) = *(const uint4*)(kl + (size_t)r * HDIM + c);
            }
        }
        __syncthreads();

        // ---- scores: warp computes 16q x 32k over d=256 ----
        {
            float c_[4][4];
#pragma unroll
            for (int i = 0; i < 4; i++)
#pragma unroll
                for (int r = 0; r < 4; r++) c_[i][r] = 0.f;

#pragma unroll
            for (int ks = 0; ks < 16; ks++) {
                uint32_t ah[4], al[4];
                ldsm4(ah, aBase + ks * 32);
                ldsm4(al, aBase + (O_QLO - O_QHI) + ks * 32);
                uint32_t bh[4][2], bl[4][2];
#pragma unroll
                for (int p = 0; p < 2; p++) {
                    uint32_t addr = bBase + (uint32_t)(p * 16 * QS) * 2 + ks * 32;
                    uint32_t r[4], q[4];
                    ldsm4(r, addr);
                    ldsm4(q, addr + (O_KLO - O_KHI));
                    bh[2 * p][0] = r[0]; bh[2 * p][1] = r[2];
                    bh[2 * p + 1][0] = r[1]; bh[2 * p + 1][1] = r[3];
                    bl[2 * p][0] = q[0]; bl[2 * p][1] = q[2];
                    bl[2 * p + 1][0] = q[1]; bl[2 * p + 1][1] = q[3];
                }
#pragma unroll
                for (int nt = 0; nt < 4; nt++) {
                    mma16816(c_[nt], ah, bh[nt]);
                    mma16816(c_[nt], ah, bl[nt]);
                    mma16816(c_[nt], al, bh[nt]);
                }
            }
            // stage S (fp32)
#pragma unroll
            for (int nt = 0; nt < 4; nt++) {
                int row = sqm * 16 + (lane >> 2);
                int col = skn * 32 + nt * 8 + (lane & 3) * 2;
                *(float2*)&S[row * SSTR + col] = make_float2(c_[nt][0], c_[nt][1]);
                *(float2*)&S[(row + 8) * SSTR + col] = make_float2(c_[nt][2], c_[nt][3]);
            }
        }
        __syncthreads();

        // ---- softmax: thread = (row = tid/4, 16-col slice = tid%4) ----
        {
            int row = tid >> 2, part = tid & 3;
            const float* mrow = mask + (size_t)b * SEQ * SEQ
                                     + (size_t)(q0 + row) * SEQ + k0 + part * 16;
            float sv[16];
            float mx = -1e30f;
#pragma unroll
            for (int i = 0; i < 16; i++) {
                sv[i] = S[row * SSTR + part * 16 + i] * 0.0625f + mrow[i];
                mx = fmaxf(mx, sv[i]);
            }
            mx = fmaxf(mx, __shfl_xor_sync(0xffffffffu, mx, 1, 4));
            mx = fmaxf(mx, __shfl_xor_sync(0xffffffffu, mx, 2, 4));
            float m_old = m_s[row];
            float m_new = fmaxf(m_old, mx);
            float sum = 0.f;
            __nv_bfloat16* phb = (__nv_bfloat16*)(smf + O_PHI) + row * PSTR + part * 16;
            __nv_bfloat16* plb = (__nv_bfloat16*)(smf + O_PLO) + row * PSTR + part * 16;
#pragma unroll
            for (int i = 0; i < 16; i++) {
                float p = __expf(sv[i] - m_new);
                sum += p;
                __nv_bfloat16 ph = __float2bfloat16(p);
                phb[i] = ph;
                plb[i] = __float2bfloat16(p - __bfloat162float(ph));
            }
            sum += __shfl_xor_sync(0xffffffffu, sum, 1, 4);
            sum += __shfl_xor_sync(0xffffffffu, sum, 2, 4);
            if (part == 0) {
                float corr = __expf(m_old - m_new);
                corr_s[row] = corr;
                l_s[row] = l_s[row] * corr + sum;
                m_s[row] = m_new;
            }
        }
        // ---- load V tile into K buffer (K consumed) ----
        {
            const __nv_bfloat16* vh = g_vhi + (size_t)(b * SEQ + k0) * HDIM;
            const __nv_bfloat16* vl = g_vlo + (size_t)(b * SEQ + k0) * HDIM;
            for (int s = tid; s < 64 * 32; s += 256) {
                int r = s >> 5, c = (s & 31) * 8;
                uint32_t d = (uint32_t)(r * QS + c) * 2;
                *(uint4*)(smf + O_KHI + d) = *(const uint4*)(vh + (size_t)r * HDIM + c);
                *(uint4*)(smf + O_KLO + d) = *(const uint4*)(vl + (size_t)r * HDIM + c);
            }
        }
        __syncthreads();

        // ---- rescale O by corr ----
#pragma unroll
        for (int mt = 0; mt < 2; mt++) {
            int r0 = pm * 32 + mt * 16 + (lane >> 2);
            float c0 = corr_s[r0], c1 = corr_s[r0 + 8];
#pragma unroll
            for (int nt = 0; nt < 8; nt++) {
                acc[mt][nt][0] *= c0; acc[mt][nt][1] *= c0;
                acc[mt][nt][2] *= c1; acc[mt][nt][3] *= c1;
            }
        }

        // ---- PV: warp computes 32q x 64d over 64 keys ----
#pragma unroll
        for (int ks = 0; ks < 4; ks++) {
            uint32_t pha[2][4], pla[2][4];
#pragma unroll
            for (int mt = 0; mt < 2; mt++) {
                uint32_t pa = pBase + (uint32_t)(mt * 16 * PSTR) * 2 + ks * 32;
                ldsm4(pha[mt], pa);
                ldsm4(pla[mt], pa + (O_PLO - O_PHI));
            }
#pragma unroll
            for (int pr = 0; pr < 4; pr++) {
                uint32_t va = vBase + (uint32_t)(ks * 16 * QS) * 2 + pr * 32;
                uint32_t rh[4], rl[4];
                ldsm4t(rh, va);
                ldsm4t(rl, va + (O_KLO - O_KHI));
                uint32_t b0h[2] = {rh[0], rh[1]}, b1h[2] = {rh[2], rh[3]};
                uint32_t b0l[2] = {rl[0], rl[1]}, b1l[2] = {rl[2], rl[3]};
#pragma unroll
                for (int mt = 0; mt < 2; mt++) {
                    mma16816(acc[mt][2 * pr],     pha[mt], b0h);
                    mma16816(acc[mt][2 * pr],     pha[mt], b0l);
                    mma16816(acc[mt][2 * pr],     pla[mt], b0h);
                    mma16816(acc[mt][2 * pr + 1], pha[mt], b1h);
                    mma16816(acc[mt][2 * pr + 1], pha[mt], b1l);
                    mma16816(acc[mt][2 * pr + 1], pla[mt], b1h);
                }
            }
        }
        __syncthreads();
    }

    // ---- epilogue: normalize, write fp32 to g_ao ----
#pragma unroll
    for (int mt = 0; mt < 2; mt++) {
        int r0 = pm * 32 + mt * 16 + (lane >> 2);
        int r1 = r0 + 8;
        float i0 = 1.0f / l_s[r0], i1 = 1.0f / l_s[r1];
#pragma unroll
        for (int nt = 0; nt < 8; nt++) {
            int col = pn * 64 + nt * 8 + (lane & 3) * 2;
            *(float2*)(g_ao + (size_t)(b * SEQ + q0 + r0) * (NH * HDIM) + h * HDIM + col) =
                make_float2(acc[mt][nt][0] * i0, acc[mt][nt][1] * i0);
            *(float2*)(g_ao + (size_t)(b * SEQ + q0 + r1) * (NH * HDIM) + h * HDIM + col) =
                make_float2(acc[mt][nt][2] * i1, acc[mt][nt][3] * i1);
        }
    }
}

// ---------------------------------------------------------------------------
extern "C" void kernel_launch(void* const* d_in, const int* in_sizes, int n_in,
                              void* d_out, int out_size) {
    const float* hidden = (const float*)d_in[0];
    const float* mask   = (const float*)d_in[1];
    const int*   pos    = (const int*)d_in[2];
    const float* Wq     = (const float*)d_in[3];
    const float* Wk     = (const float*)d_in[4];
    const float* Wv     = (const float*)d_in[5];
    const float* Wo     = (const float*)d_in[6];
    float* out = (float*)d_out;

    float *qb, *kb, *vb, *aob;
    cudaGetSymbolAddress((void**)&qb, g_q);
    cudaGetSymbolAddress((void**)&kb, g_k);
    cudaGetSymbolAddress((void**)&vb, g_v);
    cudaGetSymbolAddress((void**)&aob, g_ao);
    __nv_bfloat16 *hh, *hl, *aoh, *aol, *qh, *ql, *kh, *kl, *vh, *vl, *oh, *ol;
    cudaGetSymbolAddress((void**)&hh, g_hid_hi);
    cudaGetSymbolAddress((void**)&hl, g_hid_lo);
    cudaGetSymbolAddress((void**)&aoh, g_ao_hi);
    cudaGetSymbolAddress((void**)&aol, g_ao_lo);
    cudaGetSymbolAddress((void**)&qh, g_wq_hi);
    cudaGetSymbolAddress((void**)&ql, g_wq_lo);
    cudaGetSymbolAddress((void**)&kh, g_wk_hi);
    cudaGetSymbolAddress((void**)&kl, g_wk_lo);
    cudaGetSymbolAddress((void**)&vh, g_wv_hi);
    cudaGetSymbolAddress((void**)&vl, g_wv_lo);
    cudaGetSymbolAddress((void**)&oh, g_wo_hi);
    cudaGetSymbolAddress((void**)&ol, g_wo_lo);
    __nv_bfloat16 *vvh, *vvl;
    cudaGetSymbolAddress((void**)&vvh, g_vhi);
    cudaGetSymbolAddress((void**)&vvl, g_vlo);

    cudaFuncSetAttribute(mma_gemm, cudaFuncAttributeMaxDynamicSharedMemorySize,
                         MMA_SMEM);
    cudaFuncSetAttribute(flash_attn_tc, cudaFuncAttributeMaxDynamicSharedMemorySize,
                         FLASH_TC_SMEM);

    // RoPE table (independent)
    int ttot = MROWS * 128;
    rope_table_kernel<<<(ttot + 255) / 256, 256>>>(pos);

    // Splits: hidden (row-major) + weights (transposed to [N][K])
    int nh = MROWS * DMODEL;
    split_bf16<<<(nh + 255) / 256, 256>>>(hidden, hh, hl, nh);
    dim3 tb(32, 8);
    split_bf16_T<<<dim3(DMODEL / 32, DMODEL / 32), tb>>>(Wq, qh, ql, DMODEL, DMODEL);
    split_bf16_T<<<dim3(HDIM / 32, DMODEL / 32), tb>>>(Wk, kh, kl, DMODEL, HDIM);
    split_bf16_T<<<dim3(HDIM / 32, DMODEL / 32), tb>>>(Wv, vh, vl, DMODEL, HDIM);
    split_bf16_T<<<dim3(DMODEL / 32, DMODEL / 32), tb>>>(Wo, oh, ol, DMODEL, DMODEL);

    // Projections on tensor cores (HMMA)
    mma_gemm<<<dim3(DMODEL / 128, MROWS / 128), 256, MMA_SMEM>>>(
        hh, hl, qh, ql, qb, MROWS, DMODEL, DMODEL);
    mma_gemm<<<dim3(HDIM / 128, MROWS / 128), 256, MMA_SMEM>>>(
        hh, hl, kh, kl, kb, MROWS, HDIM, DMODEL);
    mma_gemm<<<dim3(HDIM / 128, MROWS / 128), 256, MMA_SMEM>>>(
        hh, hl, vh, vl, vb, MROWS, HDIM, DMODEL);

    // RoPE + q/k split; v split
    int rtot = MROWS * 9 * 128;
    rope_apply_split<<<(rtot + 255) / 256, 256>>>();
    int nv = MROWS * HDIM;
    split_bf16<<<(nv + 255) / 256, 256>>>(vb, vvh, vvl, nv);

    // Tensor-core flash attention
    dim3 gf(SEQ / 64, BATCH * NH);
    flash_attn_tc<<<gf, 256, FLASH_TC_SMEM>>>(mask);

    // Output projection
    split_bf16<<<(nh + 255) / 256, 256>>>(aob, aoh, aol, nh);
    mma_gemm<<<dim3(DMODEL / 128, MROWS / 128), 256, MMA_SMEM>>>(
        aoh, aol, oh, ol, out, MROWS, DMODEL, DMODEL);
}

// round 7
// speedup vs baseline: 3.5540x; 1.2173x over previous
#include <cuda_runtime.h>
#include <cuda_bf16.h>
#include <math.h>
#include <stdint.h>

#define BATCH 2
#define SEQ 2048
#define DMODEL 2048
#define NH 8
#define HDIM 256
#define MROWS (BATCH * SEQ)          // 4096
#define QKVW 2560                    // merged qkv output width (2048 q + 256 k + 256 v)

// ---------------- fp32 scratch ----------------
static __device__ float g_qkv[MROWS * QKVW];      // merged projection output
static __device__ float g_ao[MROWS * NH * HDIM];
static __device__ float2 g_rope[MROWS * 128];

// ---------------- bf16 split scratch ----------------
static __device__ __nv_bfloat16 g_hid_hi[MROWS * DMODEL];
static __device__ __nv_bfloat16 g_hid_lo[MROWS * DMODEL];
static __device__ __nv_bfloat16 g_ao_hi[MROWS * DMODEL];
static __device__ __nv_bfloat16 g_ao_lo[MROWS * DMODEL];
static __device__ __nv_bfloat16 g_wqkv_hi[QKVW * DMODEL]; // [N][K] transposed, rows: q 0..2047, k 2048..2303, v 2304..2559
static __device__ __nv_bfloat16 g_wqkv_lo[QKVW * DMODEL];
static __device__ __nv_bfloat16 g_wo_hi[DMODEL * DMODEL];
static __device__ __nv_bfloat16 g_wo_lo[DMODEL * DMODEL];
// flash attention operands (bf16 hi/lo, post-RoPE)
static __device__ __nv_bfloat16 g_qhi[MROWS * NH * HDIM];
static __device__ __nv_bfloat16 g_qlo[MROWS * NH * HDIM];
static __device__ __nv_bfloat16 g_khi[MROWS * HDIM];
static __device__ __nv_bfloat16 g_klo[MROWS * HDIM];
static __device__ __nv_bfloat16 g_vhi[MROWS * HDIM];
static __device__ __nv_bfloat16 g_vlo[MROWS * HDIM];

// ---------------------------------------------------------------------------
// Warp-MMA helpers (baseline PTX, works under compute_103)
// ---------------------------------------------------------------------------
__device__ __forceinline__ uint32_t smem_u32(const void* p) {
    uint32_t a;
    asm("{ .reg .u64 t; cvta.to.shared.u64 t, %1; cvt.u32.u64 %0, t; }"
        : "=r"(a) : "l"(p));
    return a;
}
__device__ __forceinline__ void cp16(uint32_t s, const void* g) {
    asm volatile("cp.async.ca.shared.global [%0], [%1], 16;" :: "r"(s), "l"(g));
}
__device__ __forceinline__ void cp_commit() {
    asm volatile("cp.async.commit_group;" ::: "memory");
}
__device__ __forceinline__ void ldsm4(uint32_t* r, uint32_t a) {
    asm volatile("ldmatrix.sync.aligned.m8n8.x4.shared.b16 {%0,%1,%2,%3}, [%4];"
                 : "=r"(r[0]), "=r"(r[1]), "=r"(r[2]), "=r"(r[3]) : "r"(a));
}
__device__ __forceinline__ void ldsm4t(uint32_t* r, uint32_t a) {
    asm volatile("ldmatrix.sync.aligned.m8n8.x4.trans.shared.b16 {%0,%1,%2,%3}, [%4];"
                 : "=r"(r[0]), "=r"(r[1]), "=r"(r[2]), "=r"(r[3]) : "r"(a));
}
__device__ __forceinline__ void mma16816(float* c, const uint32_t* a, const uint32_t* b) {
    asm volatile(
        "mma.sync.aligned.m16n8k16.row.col.f32.bf16.bf16.f32 "
        "{%0,%1,%2,%3}, {%4,%5,%6,%7}, {%8,%9}, {%0,%1,%2,%3};"
        : "+f"(c[0]), "+f"(c[1]), "+f"(c[2]), "+f"(c[3])
        : "r"(a[0]), "r"(a[1]), "r"(a[2]), "r"(a[3]), "r"(b[0]), "r"(b[1]));
}
__device__ __forceinline__ uint32_t pack_bf16(float x0, float x1) {
    __nv_bfloat162 v;
    v.x = __float2bfloat16(x0);
    v.y = __float2bfloat16(x1);
    return *(uint32_t*)&v;
}

// ---------------------------------------------------------------------------
// mma_gemm: C[M,N] = (Ah+Al)[M,K] @ (Bh+Bl)^T, B stored [N][K] bf16.
// bf16x3, CTA 128x128, BK=32 double-buffered cp.async. ldc parametrized.
// ---------------------------------------------------------------------------
#define RSB 40
#define TILE_B (128 * RSB * 2)
#define BUF_B (4 * TILE_B)
#define MMA_SMEM (2 * BUF_B)

__global__ void __launch_bounds__(256, 1)
mma_gemm(const __nv_bfloat16* __restrict__ Ah, const __nv_bfloat16* __restrict__ Al,
         const __nv_bfloat16* __restrict__ Bh, const __nv_bfloat16* __restrict__ Bl,
         float* __restrict__ C, int ldc, int Kd) {
    extern __shared__ char smg[];
    const uint32_t sb = smem_u32(smg);
    const int tid = threadIdx.x, wid = tid >> 5, lane = tid & 31;
    const int warp_m = wid >> 2, warp_n = wid & 3;
    const int brow = blockIdx.y * 128, bcol = blockIdx.x * 128;

    float acc[4][4][4];
#pragma unroll
    for (int i = 0; i < 4; i++)
#pragma unroll
        for (int j = 0; j < 4; j++)
#pragma unroll
            for (int r = 0; r < 4; r++) acc[i][j][r] = 0.f;

    const int KT = Kd / 32;

    auto load_tile = [&](int kt, int buf) {
        const int k0 = kt * 32;
        const uint32_t bo = sb + buf * BUF_B;
#pragma unroll
        for (int s = tid; s < 512; s += 256) {
            const int row = s >> 2, seg = s & 3;
            const uint32_t so = (uint32_t)(row * 80 + seg * 16);
            const size_t ga = (size_t)(brow + row) * Kd + k0 + seg * 8;
            const size_t gb = (size_t)(bcol + row) * Kd + k0 + seg * 8;
            cp16(bo + so,              Ah + ga);
            cp16(bo + TILE_B + so,     Al + ga);
            cp16(bo + 2 * TILE_B + so, Bh + gb);
            cp16(bo + 3 * TILE_B + so, Bl + gb);
        }
        cp_commit();
    };

    load_tile(0, 0);

    for (int kt = 0; kt < KT; kt++) {
        const int cur = kt & 1;
        if (kt + 1 < KT) {
            load_tile(kt + 1, cur ^ 1);
            asm volatile("cp.async.wait_group 1;" ::: "memory");
        } else {
            asm volatile("cp.async.wait_group 0;" ::: "memory");
        }
        __syncthreads();

        const uint32_t sA = sb + cur * BUF_B;
        const uint32_t sB = sA + 2 * TILE_B;
#pragma unroll
        for (int ks = 0; ks < 2; ks++) {
            uint32_t ah[4][4], al[4][4], bh[4][2], bl[4][2];
#pragma unroll
            for (int mt = 0; mt < 4; mt++) {
                uint32_t addr = sA + (uint32_t)((warp_m * 64 + mt * 16 + (lane & 15)) * 80
                                                + (ks * 16 + (lane >> 4) * 8) * 2);
                ldsm4(ah[mt], addr);
                ldsm4(al[mt], addr + TILE_B);
            }
#pragma unroll
            for (int p = 0; p < 2; p++) {
                uint32_t addr = sB + (uint32_t)((warp_n * 32 + p * 16 + (lane & 15)) * 80
                                                + ks * 32 + (lane >> 4) * 16);
                uint32_t r[4], q[4];
                ldsm4(r, addr);
                ldsm4(q, addr + TILE_B);
                bh[2 * p][0] = r[0]; bh[2 * p][1] = r[2];
                bh[2 * p + 1][0] = r[1]; bh[2 * p + 1][1] = r[3];
                bl[2 * p][0] = q[0]; bl[2 * p][1] = q[2];
                bl[2 * p + 1][0] = q[1]; bl[2 * p + 1][1] = q[3];
            }
#pragma unroll
            for (int mt = 0; mt < 4; mt++)
#pragma unroll
                for (int nt = 0; nt < 4; nt++) {
                    mma16816(acc[mt][nt], ah[mt], bh[nt]);
                    mma16816(acc[mt][nt], ah[mt], bl[nt]);
                    mma16816(acc[mt][nt], al[mt], bh[nt]);
                }
        }
        __syncthreads();
    }

#pragma unroll
    for (int mt = 0; mt < 4; mt++) {
#pragma unroll
        for (int nt = 0; nt < 4; nt++) {
            const int row0 = brow + warp_m * 64 + mt * 16 + (lane >> 2);
            const int col = bcol + warp_n * 32 + nt * 8 + (lane & 3) * 2;
            *(float2*)(C + (size_t)row0 * ldc + col) =
                make_float2(acc[mt][nt][0], acc[mt][nt][1]);
            *(float2*)(C + (size_t)(row0 + 8) * ldc + col) =
                make_float2(acc[mt][nt][2], acc[mt][nt][3]);
        }
    }
}

// ---------------------------------------------------------------------------
// bf16 hi/lo splits
// ---------------------------------------------------------------------------
__global__ void split_bf16(const float* __restrict__ src,
                           __nv_bfloat16* __restrict__ hi,
                           __nv_bfloat16* __restrict__ lo, int n) {
    int i = blockIdx.x * blockDim.x + threadIdx.x;
    if (i >= n) return;
    float x = src[i];
    __nv_bfloat16 h = __float2bfloat16(x);
    hi[i] = h;
    lo[i] = __float2bfloat16(x - __bfloat162float(h));
}

// strided split: src rows of `ldsrc`, take cols [coff, coff+256) -> dense [row][256]
__global__ void split_bf16_strided(const float* __restrict__ src, int ldsrc, int coff,
                                   __nv_bfloat16* __restrict__ hi,
                                   __nv_bfloat16* __restrict__ lo, int n) {
    int i = blockIdx.x * blockDim.x + threadIdx.x;
    if (i >= n) return;
    int r = i >> 8, c = i & 255;
    float x = src[(size_t)r * ldsrc + coff + c];
    __nv_bfloat16 h = __float2bfloat16(x);
    hi[i] = h;
    lo[i] = __float2bfloat16(x - __bfloat162float(h));
}

__global__ void split_bf16_T(const float* __restrict__ W,
                             __nv_bfloat16* __restrict__ hi,
                             __nv_bfloat16* __restrict__ lo, int K, int N) {
    __shared__ float tile[32][33];
    int k0 = blockIdx.y * 32, n0 = blockIdx.x * 32;
    int tx = threadIdx.x, ty = threadIdx.y;
#pragma unroll
    for (int i = 0; i < 32; i += 8)
        tile[ty + i][tx] = W[(size_t)(k0 + ty + i) * N + n0 + tx];
    __syncthreads();
#pragma unroll
    for (int i = 0; i < 32; i += 8) {
        float x = tile[tx][ty + i];
        __nv_bfloat16 h = __float2bfloat16(x);
        size_t o = (size_t)(n0 + ty + i) * K + k0 + tx;
        hi[o] = h;
        lo[o] = __float2bfloat16(x - __bfloat162float(h));
    }
}

// ---------------------------------------------------------------------------
// RoPE table; RoPE apply + split (reads merged qkv buffer)
// ---------------------------------------------------------------------------
__global__ void rope_table_kernel(const int* __restrict__ pos_ids) {
    int idx = blockIdx.x * blockDim.x + threadIdx.x;
    if (idx >= MROWS * 128) return;
    int i = idx & 127;
    int bs = idx >> 7;
    double freq = exp(-(double)i * 0.07195578415606392);
    double ang = (double)pos_ids[bs] * freq;
    double sd, cd;
    sincos(ang, &sd, &cd);
    g_rope[idx] = make_float2((float)cd, (float)sd);
}

__global__ void rope_apply_split() {
    int idx = blockIdx.x * blockDim.x + threadIdx.x;
    const int total = MROWS * 9 * 128;
    if (idx >= total) return;
    int i = idx & 127;
    int rest = idx >> 7;
    int h = rest % 9;
    int bs = rest / 9;
    float2 cs = g_rope[bs * 128 + i];

    const float* base;
    __nv_bfloat16 *dhi, *dlo;
    size_t o;
    if (h < 8) {
        base = g_qkv + (size_t)bs * QKVW + h * HDIM;
        o = (size_t)bs * (NH * HDIM) + h * HDIM;
        dhi = g_qhi; dlo = g_qlo;
    } else {
        base = g_qkv + (size_t)bs * QKVW + 2048;
        o = (size_t)bs * HDIM;
        dhi = g_khi; dlo = g_klo;
    }
    float x0 = base[i], x1 = base[i + 128];
    float y0 = x0 * cs.x - x1 * cs.y;
    float y1 = x1 * cs.x + x0 * cs.y;
    __nv_bfloat16 h0 = __float2bfloat16(y0);
    __nv_bfloat16 h1 = __float2bfloat16(y1);
    dhi[o + i] = h0;
    dlo[o + i] = __float2bfloat16(y0 - __bfloat162float(h0));
    dhi[o + i + 128] = h1;
    dlo[o + i + 128] = __float2bfloat16(y1 - __bfloat162float(h1));
}

// ---------------------------------------------------------------------------
// Tensor-core flash attention, register-resident softmax.
// CTA = 128 q for one (b,h); 8 warps; warp w owns q rows 16w..16w+15 end-to-end.
// Score C-fragments convert in-register to PV A-fragments (identical layout).
// bf16x3 on both matmuls. cp.async K/V; V prefetch overlaps softmax.
// ---------------------------------------------------------------------------
#define QS 264                 // bf16 row stride (528B, ldsm conflict-free)
#define O_QHI 0
#define O_QLO 67584
#define O_KHI 135168
#define O_KLO 168960
#define FLASH_SMEM 202752

__global__ void __launch_bounds__(256, 1)
flash_attn_tc(const float* __restrict__ mask) {
    extern __shared__ char smf[];
    const uint32_t sb = smem_u32(smf);
    const int tid = threadIdx.x, wid = tid >> 5, lane = tid & 31;
    const int q0 = blockIdx.x * 128;
    const int b = blockIdx.y >> 3, h = blockIdx.y & 7;

    // ---- Q tile (128 x 256 hi/lo) via cp.async ----
    {
        const __nv_bfloat16* qh = g_qhi + (size_t)(b * SEQ + q0) * (NH * HDIM) + h * HDIM;
        const __nv_bfloat16* ql = g_qlo + (size_t)(b * SEQ + q0) * (NH * HDIM) + h * HDIM;
        for (int s = tid; s < 4096; s += 256) {
            int r = s >> 5, c = (s & 31) * 8;
            uint32_t d = (uint32_t)(r * QS + c) * 2;
            cp16(sb + O_QHI + d, qh + (size_t)r * (NH * HDIM) + c);
            cp16(sb + O_QLO + d, ql + (size_t)r * (NH * HDIM) + c);
        }
        cp_commit();
    }

    auto load_kv = [&](const __nv_bfloat16* hs, const __nv_bfloat16* ls) {
        for (int s = tid; s < 2048; s += 256) {
            int r = s >> 5, c = (s & 31) * 8;
            uint32_t d = (uint32_t)(r * QS + c) * 2;
            cp16(sb + O_KHI + d, hs + (size_t)r * HDIM + c);
            cp16(sb + O_KLO + d, ls + (size_t)r * HDIM + c);
        }
        cp_commit();
    };

    float o_acc[32][4];
#pragma unroll
    for (int i = 0; i < 32; i++)
#pragma unroll
        for (int r = 0; r < 4; r++) o_acc[i][r] = 0.f;
    float mval[2] = {-1e30f, -1e30f}, lval[2] = {0.f, 0.f};

    const uint32_t aBase = sb + O_QHI + (uint32_t)((wid * 16 + (lane & 15)) * QS) * 2
                           + (lane >> 4) * 16;
    const uint32_t bBase = sb + O_KHI + (uint32_t)((lane & 15) * QS) * 2 + (lane >> 4) * 16;
    const uint32_t vBase = sb + O_KHI + (uint32_t)((lane & 15) * QS) * 2
                           + (uint32_t)((lane >> 4) * 8) * 2;

    // first K tile
    load_kv(g_khi + (size_t)(b * SEQ) * HDIM, g_klo + (size_t)(b * SEQ) * HDIM);
    asm volatile("cp.async.wait_group 0;" ::: "memory");
    __syncthreads();

    for (int kt = 0; kt < 32; kt++) {
        const int k0 = kt * 64;

        // ---- scores: 16q x 64k over d=256 ----
        float c_[8][4];
#pragma unroll
        for (int i = 0; i < 8; i++)
#pragma unroll
            for (int r = 0; r < 4; r++) c_[i][r] = 0.f;

#pragma unroll
        for (int ks = 0; ks < 16; ks++) {
            uint32_t ah[4], al[4];
            ldsm4(ah, aBase + ks * 32);
            ldsm4(al, aBase + (O_QLO - O_QHI) + ks * 32);
#pragma unroll
            for (int p = 0; p < 4; p++) {
                uint32_t addr = bBase + (uint32_t)(p * 16 * QS) * 2 + ks * 32;
                uint32_t r[4], q[4];
                ldsm4(r, addr);
                ldsm4(q, addr + (O_KLO - O_KHI));
                uint32_t bh0[2] = {r[0], r[2]}, bh1[2] = {r[1], r[3]};
                uint32_t bl0[2] = {q[0], q[2]}, bl1[2] = {q[1], q[3]};
                mma16816(c_[2 * p], ah, bh0);
                mma16816(c_[2 * p], ah, bl0);
                mma16816(c_[2 * p], al, bh0);
                mma16816(c_[2 * p + 1], ah, bh1);
                mma16816(c_[2 * p + 1], ah, bl1);
                mma16816(c_[2 * p + 1], al, bh1);
            }
        }
        __syncthreads();                 // all warps done reading K smem

        // ---- prefetch V into the K buffer (overlaps softmax) ----
        load_kv(g_vhi + (size_t)(b * SEQ + k0) * HDIM,
                g_vlo + (size_t)(b * SEQ + k0) * HDIM);

        // ---- softmax in registers ----
        const float* mrow = mask + (size_t)b * SEQ * SEQ
                                 + (size_t)(q0 + wid * 16 + (lane >> 2)) * SEQ
                                 + k0 + (lane & 3) * 2;
#pragma unroll
        for (int h2 = 0; h2 < 2; h2++) {
            const float* mr = mrow + (size_t)(h2 * 8) * SEQ;
            float mx = -1e30f;
#pragma unroll
            for (int nt = 0; nt < 8; nt++) {
                float2 mk = *(const float2*)(mr + nt * 8);
                float v0 = c_[nt][2 * h2] * 0.0625f + mk.x;
                float v1 = c_[nt][2 * h2 + 1] * 0.0625f + mk.y;
                c_[nt][2 * h2] = v0;
                c_[nt][2 * h2 + 1] = v1;
                mx = fmaxf(mx, fmaxf(v0, v1));
            }
            mx = fmaxf(mx, __shfl_xor_sync(0xffffffffu, mx, 1));
            mx = fmaxf(mx, __shfl_xor_sync(0xffffffffu, mx, 2));
            float m_new = fmaxf(mval[h2], mx);
            float corr = __expf(mval[h2] - m_new);
            mval[h2] = m_new;
            float sum = 0.f;
#pragma unroll
            for (int nt = 0; nt < 8; nt++) {
                float p0 = __expf(c_[nt][2 * h2] - m_new);
                float p1 = __expf(c_[nt][2 * h2 + 1] - m_new);
                c_[nt][2 * h2] = p0;
                c_[nt][2 * h2 + 1] = p1;
                sum += p0 + p1;
            }
            sum += __shfl_xor_sync(0xffffffffu, sum, 1);
            sum += __shfl_xor_sync(0xffffffffu, sum, 2);
            lval[h2] = lval[h2] * corr + sum;
#pragma unroll
            for (int nt = 0; nt < 32; nt++) {
                o_acc[nt][2 * h2] *= corr;
                o_acc[nt][2 * h2 + 1] *= corr;
            }
        }

        // ---- pack P into PV A-fragments (hi/lo), all in registers ----
        uint32_t phi[4][4], plo[4][4];
#pragma unroll
        for (int kk = 0; kk < 4; kk++) {
#pragma unroll
            for (int j = 0; j < 4; j++) {
                int nt = 2 * kk + (j >> 1);
                int rb = (j & 1) * 2;
                float x0 = c_[nt][rb], x1 = c_[nt][rb + 1];
                __nv_bfloat16 h0 = __float2bfloat16(x0);
                __nv_bfloat16 h1 = __float2bfloat16(x1);
                phi[kk][j] = pack_bf16(x0, x1);
                plo[kk][j] = pack_bf16(x0 - __bfloat162float(h0),
                                       x1 - __bfloat162float(h1));
            }
        }

        asm volatile("cp.async.wait_group 0;" ::: "memory");
        __syncthreads();                 // V tile ready

        // ---- PV: 16q x 256d over 64 keys ----
#pragma unroll
        for (int kk = 0; kk < 4; kk++) {
#pragma unroll
            for (int pr = 0; pr < 16; pr++) {
                uint32_t va = vBase + (uint32_t)(kk * 16 * QS) * 2 + pr * 32;
                uint32_t rh[4], rl[4];
                ldsm4t(rh, va);
                ldsm4t(rl, va + (O_KLO - O_KHI));
                uint32_t b0h[2] = {rh[0], rh[1]}, b1h[2] = {rh[2], rh[3]};
                uint32_t b0l[2] = {rl[0], rl[1]}, b1l[2] = {rl[2], rl[3]};
                mma16816(o_acc[2 * pr],     phi[kk], b0h);
                mma16816(o_acc[2 * pr],     phi[kk], b0l);
                mma16816(o_acc[2 * pr],     plo[kk], b0h);
                mma16816(o_acc[2 * pr + 1], phi[kk], b1h);
                mma16816(o_acc[2 * pr + 1], phi[kk], b1l);
                mma16816(o_acc[2 * pr + 1], plo[kk], b1h);
            }
        }
        __syncthreads();                 // all warps done reading V

        if (kt + 1 < 32) {
            load_kv(g_khi + (size_t)(b * SEQ + k0 + 64) * HDIM,
                    g_klo + (size_t)(b * SEQ + k0 + 64) * HDIM);
            asm volatile("cp.async.wait_group 0;" ::: "memory");
            __syncthreads();
        }
    }

    // ---- epilogue ----
    float i0 = 1.0f / lval[0], i1 = 1.0f / lval[1];
    int r0 = q0 + wid * 16 + (lane >> 2);
    float* ao0 = g_ao + (size_t)(b * SEQ + r0) * (NH * HDIM) + h * HDIM + (lane & 3) * 2;
    float* ao1 = ao0 + (size_t)8 * (NH * HDIM);
#pragma unroll
    for (int nt = 0; nt < 32; nt++) {
        *(float2*)(ao0 + nt * 8) = make_float2(o_acc[nt][0] * i0, o_acc[nt][1] * i0);
        *(float2*)(ao1 + nt * 8) = make_float2(o_acc[nt][2] * i1, o_acc[nt][3] * i1);
    }
}

// ---------------------------------------------------------------------------
extern "C" void kernel_launch(void* const* d_in, const int* in_sizes, int n_in,
                              void* d_out, int out_size) {
    const float* hidden = (const float*)d_in[0];
    const float* mask   = (const float*)d_in[1];
    const int*   pos    = (const int*)d_in[2];
    const float* Wq     = (const float*)d_in[3];
    const float* Wk     = (const float*)d_in[4];
    const float* Wv     = (const float*)d_in[5];
    const float* Wo     = (const float*)d_in[6];
    float* out = (float*)d_out;

    float *qkvb, *aob;
    cudaGetSymbolAddress((void**)&qkvb, g_qkv);
    cudaGetSymbolAddress((void**)&aob, g_ao);
    __nv_bfloat16 *hh, *hl, *aoh, *aol, *wqkvh, *wqkvl, *oh, *ol, *vvh, *vvl;
    cudaGetSymbolAddress((void**)&hh, g_hid_hi);
    cudaGetSymbolAddress((void**)&hl, g_hid_lo);
    cudaGetSymbolAddress((void**)&aoh, g_ao_hi);
    cudaGetSymbolAddress((void**)&aol, g_ao_lo);
    cudaGetSymbolAddress((void**)&wqkvh, g_wqkv_hi);
    cudaGetSymbolAddress((void**)&wqkvl, g_wqkv_lo);
    cudaGetSymbolAddress((void**)&oh, g_wo_hi);
    cudaGetSymbolAddress((void**)&ol, g_wo_lo);
    cudaGetSymbolAddress((void**)&vvh, g_vhi);
    cudaGetSymbolAddress((void**)&vvl, g_vlo);

    cudaFuncSetAttribute(mma_gemm, cudaFuncAttributeMaxDynamicSharedMemorySize,
                         MMA_SMEM);
    cudaFuncSetAttribute(flash_attn_tc, cudaFuncAttributeMaxDynamicSharedMemorySize,
                         FLASH_SMEM);

    // RoPE table (independent)
    int ttot = MROWS * 128;
    rope_table_kernel<<<(ttot + 255) / 256, 256>>>(pos);

    // Splits: hidden + weights (transposed into merged [N][K] buffer)
    int nh = MROWS * DMODEL;
    split_bf16<<<(nh + 255) / 256, 256>>>(hidden, hh, hl, nh);
    dim3 tb(32, 8);
    split_bf16_T<<<dim3(DMODEL / 32, DMODEL / 32), tb>>>(Wq, wqkvh, wqkvl, DMODEL, DMODEL);
    split_bf16_T<<<dim3(HDIM / 32, DMODEL / 32), tb>>>(
        Wk, wqkvh + (size_t)2048 * DMODEL, wqkvl + (size_t)2048 * DMODEL, DMODEL, HDIM);
    split_bf16_T<<<dim3(HDIM / 32, DMODEL / 32), tb>>>(
        Wv, wqkvh + (size_t)2304 * DMODEL, wqkvl + (size_t)2304 * DMODEL, DMODEL, HDIM);
    split_bf16_T<<<dim3(DMODEL / 32, DMODEL / 32), tb>>>(Wo, oh, ol, DMODEL, DMODEL);

    // Merged QKV projection (HMMA)
    mma_gemm<<<dim3(QKVW / 128, MROWS / 128), 256, MMA_SMEM>>>(
        hh, hl, wqkvh, wqkvl, qkvb, QKVW, DMODEL);

    // RoPE + q/k split; v split (strided from merged buffer)
    int rtot = MROWS * 9 * 128;
    rope_apply_split<<<(rtot + 255) / 256, 256>>>();
    int nv = MROWS * HDIM;
    split_bf16_strided<<<(nv + 255) / 256, 256>>>(qkvb, QKVW, 2304, vvh, vvl, nv);

    // Tensor-core flash attention (register softmax)
    dim3 gf(SEQ / 128, BATCH * NH);
    flash_attn_tc<<<gf, 256, FLASH_SMEM>>>(mask);

    // Output projection
    split_bf16<<<(nh + 255) / 256, 256>>>(aob, aoh, aol, nh);
    mma_gemm<<<dim3(DMODEL / 128, MROWS / 128), 256, MMA_SMEM>>>(
        aoh, aol, oh, ol, out, DMODEL, DMODEL);
}